// round 12
// baseline (speedup 1.0000x reference)
#include <cuda_runtime.h>
#include <math.h>

#define L_TOT 13824
#define CL    24
#define NCH   576
#define DM    128
#define NST   16

typedef unsigned long long u64t;

// ---------------- device scratch (static, no allocations) ----------------
__device__ float  g_buf[2][L_TOT * DM];  // ping-pong xc buffers [S][128], spatial
__device__ float  g_z[L_TOT * DM];       // silu(z)
__device__ float  g_xp[L_TOT * DM];      // pre-conv x part
__device__ float2 g_yc[L_TOT * DM];      // {y_local, cumdt}, SEQ order (phase1->3)
__device__ float  g_Ach[NCH * 2048];     // chunk aggregate P, chunk-major
__device__ float  g_Bch[NCH * 2048];     // chunk aggregate h_end, chunk-major
__device__ float  g_Hpref[NCH * 2048];   // exclusive prefix h0, chunk-major
__device__ volatile unsigned g_barc[16]; // monotonic grid-barrier counters

__device__ __forceinline__ float siluf(float v) { return v / (1.f + __expf(-v)); }
__device__ __forceinline__ float softplusf(float x) {
    if (x > 20.f) return x;
    return __logf(1.f + __expf(x));
}

// f32x2 packed helpers
__device__ __forceinline__ u64t pk2(float lo, float hi) {
    u64t r; asm("mov.b64 %0,{%1,%2};" : "=l"(r) : "f"(lo), "f"(hi)); return r;
}
__device__ __forceinline__ void upk2(u64t v, float& lo, float& hi) {
    asm("mov.b64 {%0,%1},%2;" : "=f"(lo), "=f"(hi) : "l"(v));
}
__device__ __forceinline__ u64t mul2_(u64t a, u64t b) {
    u64t r; asm("mul.rn.f32x2 %0,%1,%2;" : "=l"(r) : "l"(a), "l"(b)); return r;
}
__device__ __forceinline__ u64t fma2_(u64t a, u64t b, u64t c) {
    u64t r; asm("fma.rn.f32x2 %0,%1,%2,%3;" : "=l"(r) : "l"(a), "l"(b), "l"(c)); return r;
}

template<int DIR>
__device__ __forceinline__ int seq_to_spatial(int l) {
    if (DIR & 1) l = L_TOT - 1 - l;
    int i0 = l % 24;
    int t  = l / 24;
    int i1 = t % 24;
    int i2 = t / 24;
    switch (DIR >> 1) {
        case 0:  return i1 * 576 + i2 * 24 + i0;
        case 1:  return i2 * 576 + i1 * 24 + i0;
        case 2:  return i0 * 576 + i1 * 24 + i2;
        default: return i2 * 576 + i0 * 24 + i1;
    }
}

// all-576-block barrier; monotonic counter => safe across graph replays
__device__ __forceinline__ void grid_bar(int slot) {
    __syncthreads();
    if (threadIdx.x == 0) {
        __threadfence();
        unsigned old = atomicAdd((unsigned*)(g_barc + slot), 1u);
        unsigned target = old - (old % NCH) + NCH;
        while (g_barc[slot] < target) __nanosleep(32);
        __threadfence();
    }
    __syncthreads();
}

// ---------------- K0: in_proj ----------------
__global__ void __launch_bounds__(256) k_inproj(const float* __restrict__ x,
                                                const float* __restrict__ Win) {
    const int ST = 24;
    __shared__ float xs[ST * DM];
    int s0 = blockIdx.x * ST;
    for (int j = threadIdx.x; j < ST * DM; j += 256) xs[j] = x[s0 * DM + j];
    __syncthreads();
    int e = threadIdx.x;
    float acc[ST];
#pragma unroll
    for (int i = 0; i < ST; i++) acc[i] = 0.f;
    const float4* w4 = (const float4*)(Win + e * DM);
    for (int k4 = 0; k4 < DM / 4; k4++) {
        float4 w = w4[k4];
#pragma unroll
        for (int i = 0; i < ST; i++) {
            float4 xv = *(const float4*)(xs + i * DM + k4 * 4);
            acc[i] = fmaf(w.x, xv.x, fmaf(w.y, xv.y, fmaf(w.z, xv.z, fmaf(w.w, xv.w, acc[i]))));
        }
    }
    if (e < DM) {
#pragma unroll
        for (int i = 0; i < ST; i++) g_xp[(s0 + i) * DM + e] = acc[i];
    } else {
        int c = e - DM;
#pragma unroll
        for (int i = 0; i < ST; i++) g_z[(s0 + i) * DM + c] = siluf(acc[i]);
    }
}

// ---------------- K0b: depthwise conv + silu ----------------
__global__ void __launch_bounds__(512) k_conv(const float* __restrict__ cw,
                                              const float* __restrict__ cb) {
    __shared__ float cws[DM * 27];
    int tid = threadIdx.x;
    for (int j = tid; j < DM * 27; j += 512) cws[j] = cw[j];
    __syncthreads();
    int c = tid & 127;
    int s = blockIdx.x * 4 + (tid >> 7);
    int d0 = s % 24, t = s / 24, w0 = t % 24, h0 = t / 24;
    float acc = cb[c];
#pragma unroll
    for (int kh = 0; kh < 3; kh++) {
        int hh = h0 + kh - 1; if ((unsigned)hh >= 24u) continue;
#pragma unroll
        for (int kw = 0; kw < 3; kw++) {
            int ww = w0 + kw - 1; if ((unsigned)ww >= 24u) continue;
#pragma unroll
            for (int kd = 0; kd < 3; kd++) {
                int dd = d0 + kd - 1; if ((unsigned)dd >= 24u) continue;
                acc = fmaf(cws[c * 27 + kh * 9 + kw * 3 + kd],
                           g_xp[((hh * 24 + ww) * 24 + dd) * DM + c], acc);
            }
        }
    }
    g_buf[0][s * DM + c] = siluf(acc);
}

// ---------------- fused per-direction kernel -----------------------------
// smem layout (floats):
#define SM_BC   0                          // [24*32]  C/B rows, persists all phases
#define SM_U    768                        // [128*28]
#define SM_W    (SM_U + 128 * 28)          // [40*129]
#define SM_XD   (SM_W + 40 * 129)          // [40*28]
#define SM_DTW  (SM_XD + 40 * 28)          // [128*9]
#define SM_BIAS (SM_DTW + 128 * 9)         // [128]
#define SM_Q    (SM_BIAS + 128)            // [24] ints
#define SMEM_FLOATS (SM_Q + 24)
// phase2 region (aliases phase1 scratch, starts at 768 => bc_s preserved)
#define SM_A2   768
#define SM_B2   (768 + NCH * 5)
#define SM_H2   (768 + 2 * NCH * 5)

template<int DIR>
__global__ void __launch_bounds__(128, 4) k_dir(const float* __restrict__ xproj_w,
                                                const float* __restrict__ dtw_g,
                                                const float* __restrict__ dtb_g,
                                                const float* __restrict__ Alog_g,
                                                const float* __restrict__ Ds_g) {
    extern __shared__ float sm[];
    float* bc_s   = sm + SM_BC;
    float* u_s    = sm + SM_U;
    float* W_s    = sm + SM_W;
    float* xd_s   = sm + SM_XD;
    float* dtw_s  = sm + SM_DTW;
    float* bias_s = sm + SM_BIAS;
    int*   q_s    = (int*)(sm + SM_Q);

    const int tid = threadIdx.x;
    const int ci  = blockIdx.x;
    const int L0  = ci * CL;
    const float* __restrict__ xin = g_buf[DIR & 1];
    float* __restrict__ xout = g_buf[(DIR + 1) & 1];

    // ---- phase 1: load params + gather u + GEMM + dt/B/C + local scan ----
    if (tid < CL) q_s[tid] = seq_to_spatial<DIR>(L0 + tid);
    for (int j = tid; j < 40 * DM; j += 128)
        W_s[(j >> 7) * 129 + (j & 127)] = xproj_w[DIR * 40 * DM + j];
    for (int j = tid; j < DM * 8; j += 128)
        dtw_s[(j >> 3) * 9 + (j & 7)] = dtw_g[DIR * DM * 8 + j];
    if (tid < DM) bias_s[tid] = dtb_g[DIR * DM + tid];
    __syncthreads();

#pragma unroll
    for (int l = 0; l < CL; l++) u_s[tid * 28 + l] = xin[q_s[l] * DM + tid];
    __syncthreads();

    // xd(40x24) = W(40x128) @ u(128x24); 120 threads, 8 l's each
    if (tid < 120) {
        int f = tid % 40, lg = tid / 40, l0 = lg * 8;
        float acc[8];
#pragma unroll
        for (int i = 0; i < 8; i++) acc[i] = 0.f;
#pragma unroll 4
        for (int k = 0; k < DM; k++) {
            float w = W_s[f * 129 + k];
            float4 x0 = *(const float4*)(u_s + k * 28 + l0);
            float4 x1 = *(const float4*)(u_s + k * 28 + l0 + 4);
            acc[0] = fmaf(w, x0.x, acc[0]); acc[1] = fmaf(w, x0.y, acc[1]);
            acc[2] = fmaf(w, x0.z, acc[2]); acc[3] = fmaf(w, x0.w, acc[3]);
            acc[4] = fmaf(w, x1.x, acc[4]); acc[5] = fmaf(w, x1.y, acc[5]);
            acc[6] = fmaf(w, x1.z, acc[6]); acc[7] = fmaf(w, x1.w, acc[7]);
        }
#pragma unroll
        for (int i = 0; i < 8; i++) xd_s[f * 28 + l0 + i] = acc[i];
    }
    __syncthreads();
    // transpose B/C rows into bc_s[l][32]
    for (int j = tid; j < CL * 32; j += 128)
        bc_s[j] = xd_s[(8 + (j & 31)) * 28 + (j >> 5)];
    __syncthreads();

    float A_[NST];
#pragma unroll
    for (int n = 0; n < NST; n++) A_[n] = -__expf(Alog_g[(DIR * DM + tid) * NST + n]);
    float A0 = A_[0];
    bool fast = true;
#pragma unroll
    for (int n = 0; n < NST; n++)
        if (fabsf(A_[n] - (float)(n + 1) * A0) > 1e-5f * fabsf(A_[n])) fast = false;
    float Dv = Ds_g[DIR * DM + tid];

    float cum = 0.f;

    if (fast) {
        u64t h2[8];
#pragma unroll
        for (int k = 0; k < 8; k++) h2[k] = 0ull;
        // 3 groups of 8: dt/exp hoisted (independent) out of the serial recurrence
#pragma unroll
        for (int g = 0; g < 3; g++) {
            float dtl[8], e1l[8];
#pragma unroll
            for (int j = 0; j < 8; j++) {
                int l = g * 8 + j;
                float dtr = bias_s[tid];
#pragma unroll
                for (int r = 0; r < 8; r++)
                    dtr = fmaf(dtw_s[tid * 9 + r], xd_s[r * 28 + l], dtr);
                float dt = softplusf(dtr);
                dtl[j] = dt;
                e1l[j] = __expf(A0 * dt);
            }
#pragma unroll
            for (int j = 0; j < 8; j++) {
                int l = g * 8 + j;
                float u  = u_s[tid * 28 + l];
                float dt = dtl[j];
                float e1 = e1l[j];
                cum += dt;
                float e2 = e1 * e1, e4 = e2 * e2, e8 = e4 * e4;
                u64t e4p = pk2(e4, e4), e8p = pk2(e8, e8);
                u64t av[8];
                av[0] = pk2(e1, e2);
                av[1] = mul2_(av[0], pk2(e2, e2));
                av[2] = mul2_(av[0], e4p);
                av[3] = mul2_(av[1], e4p);
                av[4] = mul2_(av[0], e8p);
                av[5] = mul2_(av[1], e8p);
                av[6] = mul2_(av[2], e8p);
                av[7] = mul2_(av[3], e8p);
                float dtu = dt * u;
                u64t dtu2 = pk2(dtu, dtu);
                const ulonglong2* Bq = (const ulonglong2*)(bc_s + l * 32);
                u64t ya = 0ull, yb = 0ull;
#pragma unroll
                for (int q = 0; q < 4; q++) {
                    ulonglong2 bb = Bq[q];
                    h2[2 * q]     = fma2_(av[2 * q],     h2[2 * q],     mul2_(dtu2, bb.x));
                    h2[2 * q + 1] = fma2_(av[2 * q + 1], h2[2 * q + 1], mul2_(dtu2, bb.y));
                }
#pragma unroll
                for (int q = 0; q < 4; q++) {
                    ulonglong2 cc = Bq[4 + q];
                    ya = fma2_(h2[2 * q],     cc.x, ya);
                    yb = fma2_(h2[2 * q + 1], cc.y, yb);
                }
                u64t ys = fma2_(ya, pk2(1.f, 1.f), yb);
                float ylo, yhi; upk2(ys, ylo, yhi);
                g_yc[(L0 + l) * DM + tid] = make_float2(fmaf(u, Dv, ylo + yhi), cum);
            }
        }
        float hv[NST];
#pragma unroll
        for (int k = 0; k < 8; k++) upk2(h2[k], hv[2 * k], hv[2 * k + 1]);
        float p1 = __expf(A0 * cum);
        float p2 = p1 * p1, p4 = p2 * p2, p8 = p4 * p4;
        float P[NST];
        P[0] = p1; P[1] = p2; P[2] = p2 * p1; P[3] = p4;
        P[4] = p4 * p1; P[5] = p4 * p2; P[6] = p4 * P[2]; P[7] = p8;
        P[8] = p8 * p1; P[9] = p8 * p2; P[10] = p8 * P[2]; P[11] = p8 * p4;
        P[12] = p8 * P[4]; P[13] = p8 * P[5]; P[14] = p8 * P[6]; P[15] = p8 * p8;
        float4* pa = (float4*)(g_Ach + ci * 2048 + tid * 16);
        float4* pb = (float4*)(g_Bch + ci * 2048 + tid * 16);
#pragma unroll
        for (int q = 0; q < 4; q++) {
            pa[q] = make_float4(P[4 * q], P[4 * q + 1], P[4 * q + 2], P[4 * q + 3]);
            pb[q] = make_float4(hv[4 * q], hv[4 * q + 1], hv[4 * q + 2], hv[4 * q + 3]);
        }
    } else {
        float h[NST];
#pragma unroll
        for (int n = 0; n < NST; n++) h[n] = 0.f;
#pragma unroll
        for (int l = 0; l < CL; l++) {
            float u = u_s[tid * 28 + l];
            float dtr = bias_s[tid];
#pragma unroll
            for (int r = 0; r < 8; r++) dtr = fmaf(dtw_s[tid * 9 + r], xd_s[r * 28 + l], dtr);
            float dt = softplusf(dtr);
            cum += dt;
            float dtu = dt * u;
            float y = u * Dv;
#pragma unroll
            for (int n = 0; n < NST; n++) {
                h[n] = fmaf(__expf(A_[n] * dt), h[n], dtu * bc_s[l * 32 + n]);
                y = fmaf(h[n], bc_s[l * 32 + 16 + n], y);
            }
            g_yc[(L0 + l) * DM + tid] = make_float2(y, cum);
        }
        float P[NST];
#pragma unroll
        for (int n = 0; n < NST; n++) P[n] = __expf(A_[n] * cum);
        float4* pa = (float4*)(g_Ach + ci * 2048 + tid * 16);
        float4* pb = (float4*)(g_Bch + ci * 2048 + tid * 16);
#pragma unroll
        for (int q = 0; q < 4; q++) {
            pa[q] = make_float4(P[4 * q], P[4 * q + 1], P[4 * q + 2], P[4 * q + 3]);
            pb[q] = make_float4(h[4 * q], h[4 * q + 1], h[4 * q + 2], h[4 * q + 3]);
        }
    }

    grid_bar(DIR * 2);

    // ---- phase 2: exclusive prefix over 576 chunks (blocks 0..511, 4 lanes each)
    if (ci < 512) {
        float* A2 = sm + SM_A2;
        float* B2 = sm + SM_B2;
        float* H2 = sm + SM_H2;
        const int gw0 = ci * 4;
        for (int j = tid; j < NCH * 4; j += 128) {
            int c = j >> 2, w = j & 3;
            A2[c * 5 + w] = g_Ach[c * 2048 + gw0 + w];
            B2[c * 5 + w] = g_Bch[c * 2048 + gw0 + w];
        }
        __syncthreads();
        int w = tid >> 5, lane = tid & 31;
        const int PT = NCH / 32;     // 18
        float Ag = 1.f, Bg = 0.f;
        int c0 = lane * PT;
        for (int k = 0; k < PT; k++) {
            float a = A2[(c0 + k) * 5 + w];
            float b = B2[(c0 + k) * 5 + w];
            Bg = fmaf(a, Bg, b);
            Ag *= a;
        }
#pragma unroll
        for (int d = 1; d < 32; d <<= 1) {
            float aL = __shfl_up_sync(0xffffffffu, Ag, d);
            float bL = __shfl_up_sync(0xffffffffu, Bg, d);
            if (lane >= d) { Bg = fmaf(Ag, bL, Bg); Ag *= aL; }
        }
        float hp = __shfl_up_sync(0xffffffffu, Bg, 1);
        float h = (lane == 0) ? 0.f : hp;
        for (int k = 0; k < PT; k++) {
            H2[(c0 + k) * 5 + w] = h;
            h = fmaf(A2[(c0 + k) * 5 + w], h, B2[(c0 + k) * 5 + w]);
        }
        __syncthreads();
        for (int j = tid; j < NCH * 4; j += 128) {
            int c = j >> 2, w2 = j & 3;
            g_Hpref[c * 2048 + gw0 + w2] = H2[c * 5 + w2];
        }
    }

    grid_bar(DIR * 2 + 1);

    // ---- phase 3: closed-form correction + scatter to spatial ----
    float h0[NST];
    {
        const float4* hp4 = (const float4*)(g_Hpref + ci * 2048 + tid * 16);
#pragma unroll
        for (int q = 0; q < 4; q++) {
            float4 v = hp4[q];
            h0[4 * q] = v.x; h0[4 * q + 1] = v.y; h0[4 * q + 2] = v.z; h0[4 * q + 3] = v.w;
        }
    }
    if (fast) {
        u64t h0p[8];
#pragma unroll
        for (int k = 0; k < 8; k++) h0p[k] = pk2(h0[2 * k], h0[2 * k + 1]);
#pragma unroll
        for (int l = 0; l < CL; l++) {
            float2 yc = g_yc[(L0 + l) * DM + tid];
            float e1 = __expf(A0 * yc.y);
            float e2 = e1 * e1, e4 = e2 * e2, e8 = e4 * e4;
            u64t e4p = pk2(e4, e4), e8p = pk2(e8, e8);
            u64t av[8];
            av[0] = pk2(e1, e2);
            av[1] = mul2_(av[0], pk2(e2, e2));
            av[2] = mul2_(av[0], e4p);
            av[3] = mul2_(av[1], e4p);
            av[4] = mul2_(av[0], e8p);
            av[5] = mul2_(av[1], e8p);
            av[6] = mul2_(av[2], e8p);
            av[7] = mul2_(av[3], e8p);
            const ulonglong2* Cq = (const ulonglong2*)(bc_s + l * 32 + 16);
            u64t acc = 0ull;
#pragma unroll
            for (int q = 0; q < 4; q++) {
                ulonglong2 cc = Cq[q];
                acc = fma2_(mul2_(h0p[2 * q],     av[2 * q]),     cc.x, acc);
                acc = fma2_(mul2_(h0p[2 * q + 1], av[2 * q + 1]), cc.y, acc);
            }
            float lo, hi; upk2(acc, lo, hi);
            xout[seq_to_spatial<DIR>(L0 + l) * DM + tid] = yc.x + lo + hi;
        }
    } else {
#pragma unroll
        for (int l = 0; l < CL; l++) {
            float2 yc = g_yc[(L0 + l) * DM + tid];
            float y = yc.x;
#pragma unroll
            for (int n = 0; n < NST; n++)
                y = fmaf(h0[n] * __expf(A_[n] * yc.y), bc_s[l * 32 + 16 + n], y);
            xout[seq_to_spatial<DIR>(L0 + l) * DM + tid] = y;
        }
    }
}

// ---------------- K4: LayerNorm + gate + out_proj ------------------------
__global__ void __launch_bounds__(128) k_final(const float* __restrict__ gamma,
                                               const float* __restrict__ beta,
                                               const float* __restrict__ Wout,
                                               float* __restrict__ out) {
    extern __shared__ float sm[];
    float* ym = sm;                   // [16][132]
    float* Wt = sm + 16 * 132;        // [128][129]
    __shared__ float mu_s[16], rs_s[16];
    const int tid = threadIdx.x;
    const int s0 = blockIdx.x * 16;

    for (int j = tid; j < 16 * DM; j += 128) {
        int si = j >> 7, c = j & 127;
        ym[si * 132 + c] = g_buf[0][(s0 + si) * DM + c];
    }
    for (int j = tid; j < DM * DM; j += 128) {
        int c = j >> 7, e = j & 127;
        Wt[e * 129 + c] = Wout[j];
    }
    __syncthreads();

    if (tid < 16) {
        float m = 0.f;
        for (int c = 0; c < DM; c++) m += ym[tid * 132 + c];
        m *= (1.f / DM);
        float v = 0.f;
        for (int c = 0; c < DM; c++) { float d = ym[tid * 132 + c] - m; v = fmaf(d, d, v); }
        v *= (1.f / DM);
        mu_s[tid] = m;
        rs_s[tid] = rsqrtf(v + 1e-5f);
    }
    __syncthreads();

    for (int j = tid; j < 16 * DM; j += 128) {
        int si = j >> 7, c = j & 127;
        float v = (ym[si * 132 + c] - mu_s[si]) * rs_s[si] * gamma[c] + beta[c];
        ym[si * 132 + c] = v * g_z[(s0 + si) * DM + c];
    }
    __syncthreads();

    float acc[16];
#pragma unroll
    for (int i = 0; i < 16; i++) acc[i] = 0.f;
    for (int e4 = 0; e4 < DM / 4; e4++) {
        float w0 = Wt[(e4 * 4 + 0) * 129 + tid];
        float w1 = Wt[(e4 * 4 + 1) * 129 + tid];
        float w2 = Wt[(e4 * 4 + 2) * 129 + tid];
        float w3 = Wt[(e4 * 4 + 3) * 129 + tid];
#pragma unroll
        for (int si = 0; si < 16; si++) {
            float4 yv = *(const float4*)(ym + si * 132 + e4 * 4);
            acc[si] = fmaf(w0, yv.x, fmaf(w1, yv.y, fmaf(w2, yv.z, fmaf(w3, yv.w, acc[si]))));
        }
    }
#pragma unroll
    for (int si = 0; si < 16; si++) out[(s0 + si) * DM + tid] = acc[si];
}

// ---------------- launch ----------------
#define SMD (SMEM_FLOATS * 4)
#define SM4 ((16 * 132 + 128 * 129) * 4)

extern "C" void kernel_launch(void* const* d_in, const int* in_sizes, int n_in,
                              void* d_out, int out_size) {
    const float* x         = (const float*)d_in[0];
    const float* in_proj_w = (const float*)d_in[1];
    const float* conv_w    = (const float*)d_in[2];
    const float* conv_b    = (const float*)d_in[3];
    const float* xproj_w   = (const float*)d_in[4];
    const float* dtw       = (const float*)d_in[5];
    const float* dtb       = (const float*)d_in[6];
    const float* A_logs    = (const float*)d_in[7];
    const float* Ds        = (const float*)d_in[8];
    const float* ln_g      = (const float*)d_in[9];
    const float* ln_b      = (const float*)d_in[10];
    const float* out_w     = (const float*)d_in[11];
    float* out = (float*)d_out;

#define SETA(K, S) cudaFuncSetAttribute(K, cudaFuncAttributeMaxDynamicSharedMemorySize, S)
    SETA(k_dir<0>, SMD); SETA(k_dir<1>, SMD); SETA(k_dir<2>, SMD); SETA(k_dir<3>, SMD);
    SETA(k_dir<4>, SMD); SETA(k_dir<5>, SMD); SETA(k_dir<6>, SMD); SETA(k_dir<7>, SMD);
    SETA(k_final, SM4);
#undef SETA

    k_inproj<<<L_TOT / 24, 256>>>(x, in_proj_w);
    k_conv<<<L_TOT / 4, 512>>>(conv_w, conv_b);

    k_dir<0><<<NCH, 128, SMD>>>(xproj_w, dtw, dtb, A_logs, Ds);
    k_dir<1><<<NCH, 128, SMD>>>(xproj_w, dtw, dtb, A_logs, Ds);
    k_dir<2><<<NCH, 128, SMD>>>(xproj_w, dtw, dtb, A_logs, Ds);
    k_dir<3><<<NCH, 128, SMD>>>(xproj_w, dtw, dtb, A_logs, Ds);
    k_dir<4><<<NCH, 128, SMD>>>(xproj_w, dtw, dtb, A_logs, Ds);
    k_dir<5><<<NCH, 128, SMD>>>(xproj_w, dtw, dtb, A_logs, Ds);
    k_dir<6><<<NCH, 128, SMD>>>(xproj_w, dtw, dtb, A_logs, Ds);
    k_dir<7><<<NCH, 128, SMD>>>(xproj_w, dtw, dtb, A_logs, Ds);

    k_final<<<L_TOT / 16, 128, SM4>>>(ln_g, ln_b, out_w, out);
}

// round 13
// speedup vs baseline: 1.1077x; 1.1077x over previous
#include <cuda_runtime.h>
#include <math.h>

#define L_TOT 13824
#define CL    24
#define NCH   576
#define DM    128
#define NST   16

typedef unsigned long long u64t;

// ---------------- device scratch (static, no allocations) ----------------
__device__ float g_buf[2][L_TOT * DM];   // ping-pong xc buffers [S][128], spatial
__device__ float g_z[L_TOT * DM];        // silu(z)
__device__ float g_xp[L_TOT * DM];       // pre-conv x part
__device__ float g_Ach[NCH * 2048];      // chunk aggregate P, chunk-major
__device__ float g_Bch[NCH * 2048];      // chunk aggregate h_end, chunk-major
__device__ float g_Hpref[NCH * 2048];    // exclusive prefix h0, chunk-major
__device__ volatile unsigned g_barc[16]; // monotonic grid-barrier counters

__device__ __forceinline__ float siluf(float v) { return v / (1.f + __expf(-v)); }
__device__ __forceinline__ float softplusf(float x) {
    if (x > 20.f) return x;
    return __logf(1.f + __expf(x));
}

// f32x2 packed helpers
__device__ __forceinline__ u64t pk2(float lo, float hi) {
    u64t r; asm("mov.b64 %0,{%1,%2};" : "=l"(r) : "f"(lo), "f"(hi)); return r;
}
__device__ __forceinline__ void upk2(u64t v, float& lo, float& hi) {
    asm("mov.b64 {%0,%1},%2;" : "=f"(lo), "=f"(hi) : "l"(v));
}
__device__ __forceinline__ u64t mul2_(u64t a, u64t b) {
    u64t r; asm("mul.rn.f32x2 %0,%1,%2;" : "=l"(r) : "l"(a), "l"(b)); return r;
}
__device__ __forceinline__ u64t fma2_(u64t a, u64t b, u64t c) {
    u64t r; asm("fma.rn.f32x2 %0,%1,%2,%3;" : "=l"(r) : "l"(a), "l"(b), "l"(c)); return r;
}

template<int DIR>
__device__ __forceinline__ int seq_to_spatial(int l) {
    if (DIR & 1) l = L_TOT - 1 - l;
    int i0 = l % 24;
    int t  = l / 24;
    int i1 = t % 24;
    int i2 = t / 24;
    switch (DIR >> 1) {
        case 0:  return i1 * 576 + i2 * 24 + i0;
        case 1:  return i2 * 576 + i1 * 24 + i0;
        case 2:  return i0 * 576 + i1 * 24 + i2;
        default: return i2 * 576 + i0 * 24 + i1;
    }
}

// all-576-block barrier; monotonic counter => safe across graph replays
__device__ __forceinline__ void grid_bar(int slot) {
    __syncthreads();
    if (threadIdx.x == 0) {
        __threadfence();
        unsigned old = atomicAdd((unsigned*)(g_barc + slot), 1u);
        unsigned target = old - (old % NCH) + NCH;
        while (g_barc[slot] < target) __nanosleep(32);
        __threadfence();
    }
    __syncthreads();
}

// ---------------- K0: in_proj ----------------
__global__ void __launch_bounds__(256) k_inproj(const float* __restrict__ x,
                                                const float* __restrict__ Win) {
    const int ST = 24;
    __shared__ float xs[ST * DM];
    int s0 = blockIdx.x * ST;
    for (int j = threadIdx.x; j < ST * DM; j += 256) xs[j] = x[s0 * DM + j];
    __syncthreads();
    int e = threadIdx.x;
    float acc[ST];
#pragma unroll
    for (int i = 0; i < ST; i++) acc[i] = 0.f;
    const float4* w4 = (const float4*)(Win + e * DM);
    for (int k4 = 0; k4 < DM / 4; k4++) {
        float4 w = w4[k4];
#pragma unroll
        for (int i = 0; i < ST; i++) {
            float4 xv = *(const float4*)(xs + i * DM + k4 * 4);
            acc[i] = fmaf(w.x, xv.x, fmaf(w.y, xv.y, fmaf(w.z, xv.z, fmaf(w.w, xv.w, acc[i]))));
        }
    }
    if (e < DM) {
#pragma unroll
        for (int i = 0; i < ST; i++) g_xp[(s0 + i) * DM + e] = acc[i];
    } else {
        int c = e - DM;
#pragma unroll
        for (int i = 0; i < ST; i++) g_z[(s0 + i) * DM + c] = siluf(acc[i]);
    }
}

// ---------------- K0b: depthwise conv + silu ----------------
__global__ void __launch_bounds__(512) k_conv(const float* __restrict__ cw,
                                              const float* __restrict__ cb) {
    __shared__ float cws[DM * 27];
    int tid = threadIdx.x;
    for (int j = tid; j < DM * 27; j += 512) cws[j] = cw[j];
    __syncthreads();
    int c = tid & 127;
    int s = blockIdx.x * 4 + (tid >> 7);
    int d0 = s % 24, t = s / 24, w0 = t % 24, h0 = t / 24;
    float acc = cb[c];
#pragma unroll
    for (int kh = 0; kh < 3; kh++) {
        int hh = h0 + kh - 1; if ((unsigned)hh >= 24u) continue;
#pragma unroll
        for (int kw = 0; kw < 3; kw++) {
            int ww = w0 + kw - 1; if ((unsigned)ww >= 24u) continue;
#pragma unroll
            for (int kd = 0; kd < 3; kd++) {
                int dd = d0 + kd - 1; if ((unsigned)dd >= 24u) continue;
                acc = fmaf(cws[c * 27 + kh * 9 + kw * 3 + kd],
                           g_xp[((hh * 24 + ww) * 24 + dd) * DM + c], acc);
            }
        }
    }
    g_buf[0][s * DM + c] = siluf(acc);
}

// ---------------- fused per-direction kernel -----------------------------
// smem layout (floats):
#define SM_BC   0                          // [24*32]  C/B rows, persists all phases
#define SM_U    768                        // [24][132] u tile, l-major (conflict-free)
#define SM_W    (SM_U + 24 * 132)          // [128][41] W transposed (k-major)
#define SM_XD   (SM_W + 128 * 41)          // [40][28]
#define SM_DTW  (SM_XD + 40 * 28)          // [128][9]
#define SM_BIAS (SM_DTW + 128 * 9)         // [128]
#define SM_Q    (SM_BIAS + 128)            // [24] ints
#define SMEM_FLOATS (SM_Q + 24)
// phase2 region (aliases phase1 scratch, starts at 768 => bc_s preserved)
#define SM_A2   768
#define SM_B2   (768 + NCH * 5)
#define SM_H2   (768 + 2 * NCH * 5)

template<int DIR>
__global__ void __launch_bounds__(128, 4) k_dir(const float* __restrict__ xproj_w,
                                                const float* __restrict__ dtw_g,
                                                const float* __restrict__ dtb_g,
                                                const float* __restrict__ Alog_g,
                                                const float* __restrict__ Ds_g) {
    extern __shared__ float sm[];
    float* bc_s   = sm + SM_BC;
    float* u_s    = sm + SM_U;
    float* W_s    = sm + SM_W;
    float* xd_s   = sm + SM_XD;
    float* dtw_s  = sm + SM_DTW;
    float* bias_s = sm + SM_BIAS;
    int*   q_s    = (int*)(sm + SM_Q);

    const int tid = threadIdx.x;
    const int ci  = blockIdx.x;
    const int L0  = ci * CL;
    const float* __restrict__ xin = g_buf[DIR & 1];
    float* __restrict__ xout = g_buf[(DIR + 1) & 1];

    // ---- phase 1: load params + gather u + GEMM + dt/B/C + local scan ----
    if (tid < CL) q_s[tid] = seq_to_spatial<DIR>(L0 + tid);
    // W transposed: W_s[k*41 + f] = xproj_w[f*128 + k]; writes stride 41 (odd) -> conflict-free
    for (int j = tid; j < 40 * DM; j += 128) {
        int f = j >> 7, k = j & 127;
        W_s[k * 41 + f] = xproj_w[DIR * 40 * DM + j];
    }
    for (int j = tid; j < DM * 8; j += 128)
        dtw_s[(j >> 3) * 9 + (j & 7)] = dtw_g[DIR * DM * 8 + j];
    if (tid < DM) bias_s[tid] = dtb_g[DIR * DM + tid];
    __syncthreads();

    // gather u into [l][132] (coalesced global read, conflict-free smem write)
#pragma unroll
    for (int l = 0; l < CL; l++) u_s[l * 132 + tid] = xin[q_s[l] * DM + tid];
    __syncthreads();

    // xd(40x24) = W(40x128) @ u(128x24); 120 threads, 8 l's each
    // u read as broadcast LDS.128 along k; W scalar reads conflict-free (stride 41)
    if (tid < 120) {
        int f = tid % 40, lg = tid / 40, l0 = lg * 8;
        float acc[8];
#pragma unroll
        for (int i = 0; i < 8; i++) acc[i] = 0.f;
#pragma unroll 4
        for (int k4 = 0; k4 < 32; k4++) {
            float w0 = W_s[(4 * k4 + 0) * 41 + f];
            float w1 = W_s[(4 * k4 + 1) * 41 + f];
            float w2 = W_s[(4 * k4 + 2) * 41 + f];
            float w3 = W_s[(4 * k4 + 3) * 41 + f];
#pragma unroll
            for (int i = 0; i < 8; i++) {
                float4 uv = *(const float4*)(u_s + (l0 + i) * 132 + 4 * k4);
                acc[i] = fmaf(w0, uv.x, fmaf(w1, uv.y, fmaf(w2, uv.z, fmaf(w3, uv.w, acc[i]))));
            }
        }
#pragma unroll
        for (int i = 0; i < 8; i++) xd_s[f * 28 + l0 + i] = acc[i];
    }
    __syncthreads();
    // transpose B/C rows into bc_s[l][32]
    for (int j = tid; j < CL * 32; j += 128)
        bc_s[j] = xd_s[(8 + (j & 31)) * 28 + (j >> 5)];
    __syncthreads();

    float A_[NST];
    {
        const float4* a4 = (const float4*)(Alog_g + (DIR * DM + tid) * NST);
#pragma unroll
        for (int q = 0; q < 4; q++) {
            float4 v = a4[q];
            A_[4 * q]     = -__expf(v.x);
            A_[4 * q + 1] = -__expf(v.y);
            A_[4 * q + 2] = -__expf(v.z);
            A_[4 * q + 3] = -__expf(v.w);
        }
    }
    float A0 = A_[0];
    bool fast = true;
#pragma unroll
    for (int n = 0; n < NST; n++)
        if (fabsf(A_[n] - (float)(n + 1) * A0) > 1e-5f * fabsf(A_[n])) fast = false;
    float Dv = Ds_g[DIR * DM + tid];

    float yv[CL], cumv[CL];
    float cum = 0.f;

    if (fast) {
        u64t h2[8];
#pragma unroll
        for (int k = 0; k < 8; k++) h2[k] = 0ull;
        // 3 groups of 8: dt/exp hoisted (independent) out of the serial recurrence
#pragma unroll
        for (int g = 0; g < 3; g++) {
            float dtl[8], e1l[8];
#pragma unroll
            for (int j = 0; j < 8; j++) {
                int l = g * 8 + j;
                float dtr = bias_s[tid];
#pragma unroll
                for (int r = 0; r < 8; r++)
                    dtr = fmaf(dtw_s[tid * 9 + r], xd_s[r * 28 + l], dtr);
                float dt = softplusf(dtr);
                dtl[j] = dt;
                e1l[j] = __expf(A0 * dt);
            }
#pragma unroll
            for (int j = 0; j < 8; j++) {
                int l = g * 8 + j;
                float u  = u_s[l * 132 + tid];
                float dt = dtl[j];
                float e1 = e1l[j];
                cum += dt; cumv[l] = cum;
                float e2 = e1 * e1, e4 = e2 * e2, e8 = e4 * e4;
                u64t e4p = pk2(e4, e4), e8p = pk2(e8, e8);
                u64t av[8];
                av[0] = pk2(e1, e2);
                av[1] = mul2_(av[0], pk2(e2, e2));
                av[2] = mul2_(av[0], e4p);
                av[3] = mul2_(av[1], e4p);
                av[4] = mul2_(av[0], e8p);
                av[5] = mul2_(av[1], e8p);
                av[6] = mul2_(av[2], e8p);
                av[7] = mul2_(av[3], e8p);
                float dtu = dt * u;
                u64t dtu2 = pk2(dtu, dtu);
                const ulonglong2* Bq = (const ulonglong2*)(bc_s + l * 32);
                u64t ya = 0ull, yb = 0ull;
#pragma unroll
                for (int q = 0; q < 4; q++) {
                    ulonglong2 bb = Bq[q];
                    h2[2 * q]     = fma2_(av[2 * q],     h2[2 * q],     mul2_(dtu2, bb.x));
                    h2[2 * q + 1] = fma2_(av[2 * q + 1], h2[2 * q + 1], mul2_(dtu2, bb.y));
                }
#pragma unroll
                for (int q = 0; q < 4; q++) {
                    ulonglong2 cc = Bq[4 + q];
                    ya = fma2_(h2[2 * q],     cc.x, ya);
                    yb = fma2_(h2[2 * q + 1], cc.y, yb);
                }
                u64t ys = fma2_(ya, pk2(1.f, 1.f), yb);
                float ylo, yhi; upk2(ys, ylo, yhi);
                yv[l] = fmaf(u, Dv, ylo + yhi);
            }
        }
        float hv[NST];
#pragma unroll
        for (int k = 0; k < 8; k++) upk2(h2[k], hv[2 * k], hv[2 * k + 1]);
        float p1 = __expf(A0 * cum);
        float p2 = p1 * p1, p4 = p2 * p2, p8 = p4 * p4;
        float P[NST];
        P[0] = p1; P[1] = p2; P[2] = p2 * p1; P[3] = p4;
        P[4] = p4 * p1; P[5] = p4 * p2; P[6] = p4 * P[2]; P[7] = p8;
        P[8] = p8 * p1; P[9] = p8 * p2; P[10] = p8 * P[2]; P[11] = p8 * p4;
        P[12] = p8 * P[4]; P[13] = p8 * P[5]; P[14] = p8 * P[6]; P[15] = p8 * p8;
        float4* pa = (float4*)(g_Ach + ci * 2048 + tid * 16);
        float4* pb = (float4*)(g_Bch + ci * 2048 + tid * 16);
#pragma unroll
        for (int q = 0; q < 4; q++) {
            pa[q] = make_float4(P[4 * q], P[4 * q + 1], P[4 * q + 2], P[4 * q + 3]);
            pb[q] = make_float4(hv[4 * q], hv[4 * q + 1], hv[4 * q + 2], hv[4 * q + 3]);
        }
    } else {
        float h[NST];
#pragma unroll
        for (int n = 0; n < NST; n++) h[n] = 0.f;
#pragma unroll
        for (int l = 0; l < CL; l++) {
            float u = u_s[l * 132 + tid];
            float dtr = bias_s[tid];
#pragma unroll
            for (int r = 0; r < 8; r++) dtr = fmaf(dtw_s[tid * 9 + r], xd_s[r * 28 + l], dtr);
            float dt = softplusf(dtr);
            cum += dt; cumv[l] = cum;
            float dtu = dt * u;
            float y = u * Dv;
#pragma unroll
            for (int n = 0; n < NST; n++) {
                h[n] = fmaf(__expf(A_[n] * dt), h[n], dtu * bc_s[l * 32 + n]);
                y = fmaf(h[n], bc_s[l * 32 + 16 + n], y);
            }
            yv[l] = y;
        }
        float P[NST];
#pragma unroll
        for (int n = 0; n < NST; n++) P[n] = __expf(A_[n] * cum);
        float4* pa = (float4*)(g_Ach + ci * 2048 + tid * 16);
        float4* pb = (float4*)(g_Bch + ci * 2048 + tid * 16);
#pragma unroll
        for (int q = 0; q < 4; q++) {
            pa[q] = make_float4(P[4 * q], P[4 * q + 1], P[4 * q + 2], P[4 * q + 3]);
            pb[q] = make_float4(h[4 * q], h[4 * q + 1], h[4 * q + 2], h[4 * q + 3]);
        }
    }

    grid_bar(DIR * 2);

    // ---- phase 2: exclusive prefix over 576 chunks (blocks 0..511, 4 lanes each)
    if (ci < 512) {
        float* A2 = sm + SM_A2;
        float* B2 = sm + SM_B2;
        float* H2 = sm + SM_H2;
        const int gw0 = ci * 4;
        for (int j = tid; j < NCH * 4; j += 128) {
            int c = j >> 2, w = j & 3;
            A2[c * 5 + w] = g_Ach[c * 2048 + gw0 + w];
            B2[c * 5 + w] = g_Bch[c * 2048 + gw0 + w];
        }
        __syncthreads();
        int w = tid >> 5, lane = tid & 31;
        const int PT = NCH / 32;     // 18
        float Ag = 1.f, Bg = 0.f;
        int c0 = lane * PT;
        for (int k = 0; k < PT; k++) {
            float a = A2[(c0 + k) * 5 + w];
            float b = B2[(c0 + k) * 5 + w];
            Bg = fmaf(a, Bg, b);
            Ag *= a;
        }
#pragma unroll
        for (int d = 1; d < 32; d <<= 1) {
            float aL = __shfl_up_sync(0xffffffffu, Ag, d);
            float bL = __shfl_up_sync(0xffffffffu, Bg, d);
            if (lane >= d) { Bg = fmaf(Ag, bL, Bg); Ag *= aL; }
        }
        float hp = __shfl_up_sync(0xffffffffu, Bg, 1);
        float h = (lane == 0) ? 0.f : hp;
        for (int k = 0; k < PT; k++) {
            H2[(c0 + k) * 5 + w] = h;
            h = fmaf(A2[(c0 + k) * 5 + w], h, B2[(c0 + k) * 5 + w]);
        }
        __syncthreads();
        for (int j = tid; j < NCH * 4; j += 128) {
            int c = j >> 2, w2 = j & 3;
            g_Hpref[c * 2048 + gw0 + w2] = H2[c * 5 + w2];
        }
    }

    grid_bar(DIR * 2 + 1);

    // ---- phase 3: closed-form correction + scatter to spatial ----
    float h0[NST];
    {
        const float4* hp4 = (const float4*)(g_Hpref + ci * 2048 + tid * 16);
#pragma unroll
        for (int q = 0; q < 4; q++) {
            float4 v = hp4[q];
            h0[4 * q] = v.x; h0[4 * q + 1] = v.y; h0[4 * q + 2] = v.z; h0[4 * q + 3] = v.w;
        }
    }
    if (fast) {
        u64t h0p[8];
#pragma unroll
        for (int k = 0; k < 8; k++) h0p[k] = pk2(h0[2 * k], h0[2 * k + 1]);
#pragma unroll
        for (int l = 0; l < CL; l++) {
            float e1 = __expf(A0 * cumv[l]);
            float e2 = e1 * e1, e4 = e2 * e2, e8 = e4 * e4;
            u64t e4p = pk2(e4, e4), e8p = pk2(e8, e8);
            u64t av[8];
            av[0] = pk2(e1, e2);
            av[1] = mul2_(av[0], pk2(e2, e2));
            av[2] = mul2_(av[0], e4p);
            av[3] = mul2_(av[1], e4p);
            av[4] = mul2_(av[0], e8p);
            av[5] = mul2_(av[1], e8p);
            av[6] = mul2_(av[2], e8p);
            av[7] = mul2_(av[3], e8p);
            const ulonglong2* Cq = (const ulonglong2*)(bc_s + l * 32 + 16);
            u64t acc = 0ull;
#pragma unroll
            for (int q = 0; q < 4; q++) {
                ulonglong2 cc = Cq[q];
                acc = fma2_(mul2_(h0p[2 * q],     av[2 * q]),     cc.x, acc);
                acc = fma2_(mul2_(h0p[2 * q + 1], av[2 * q + 1]), cc.y, acc);
            }
            float lo, hi; upk2(acc, lo, hi);
            xout[seq_to_spatial<DIR>(L0 + l) * DM + tid] = yv[l] + lo + hi;
        }
    } else {
#pragma unroll
        for (int l = 0; l < CL; l++) {
            float y = yv[l];
#pragma unroll
            for (int n = 0; n < NST; n++)
                y = fmaf(h0[n] * __expf(A_[n] * cumv[l]), bc_s[l * 32 + 16 + n], y);
            xout[seq_to_spatial<DIR>(L0 + l) * DM + tid] = y;
        }
    }
}

// ---------------- K4: LayerNorm + gate + out_proj ------------------------
__global__ void __launch_bounds__(128) k_final(const float* __restrict__ gamma,
                                               const float* __restrict__ beta,
                                               const float* __restrict__ Wout,
                                               float* __restrict__ out) {
    extern __shared__ float sm[];
    float* ym = sm;                   // [16][132]
    float* Wt = sm + 16 * 132;        // [128][129]
    __shared__ float mu_s[16], rs_s[16];
    const int tid = threadIdx.x;
    const int s0 = blockIdx.x * 16;

    for (int j = tid; j < 16 * DM; j += 128) {
        int si = j >> 7, c = j & 127;
        ym[si * 132 + c] = g_buf[0][(s0 + si) * DM + c];
    }
    for (int j = tid; j < DM * DM; j += 128) {
        int c = j >> 7, e = j & 127;
        Wt[e * 129 + c] = Wout[j];
    }
    __syncthreads();

    if (tid < 16) {
        float m = 0.f;
        for (int c = 0; c < DM; c++) m += ym[tid * 132 + c];
        m *= (1.f / DM);
        float v = 0.f;
        for (int c = 0; c < DM; c++) { float d = ym[tid * 132 + c] - m; v = fmaf(d, d, v); }
        v *= (1.f / DM);
        mu_s[tid] = m;
        rs_s[tid] = rsqrtf(v + 1e-5f);
    }
    __syncthreads();

    for (int j = tid; j < 16 * DM; j += 128) {
        int si = j >> 7, c = j & 127;
        float v = (ym[si * 132 + c] - mu_s[si]) * rs_s[si] * gamma[c] + beta[c];
        ym[si * 132 + c] = v * g_z[(s0 + si) * DM + c];
    }
    __syncthreads();

    float acc[16];
#pragma unroll
    for (int i = 0; i < 16; i++) acc[i] = 0.f;
    for (int e4 = 0; e4 < DM / 4; e4++) {
        float w0 = Wt[(e4 * 4 + 0) * 129 + tid];
        float w1 = Wt[(e4 * 4 + 1) * 129 + tid];
        float w2 = Wt[(e4 * 4 + 2) * 129 + tid];
        float w3 = Wt[(e4 * 4 + 3) * 129 + tid];
#pragma unroll
        for (int si = 0; si < 16; si++) {
            float4 yv = *(const float4*)(ym + si * 132 + e4 * 4);
            acc[si] = fmaf(w0, yv.x, fmaf(w1, yv.y, fmaf(w2, yv.z, fmaf(w3, yv.w, acc[si]))));
        }
    }
#pragma unroll
    for (int si = 0; si < 16; si++) out[(s0 + si) * DM + tid] = acc[si];
}

// ---------------- launch ----------------
#define SMD (SMEM_FLOATS * 4)
#define SM4 ((16 * 132 + 128 * 129) * 4)

extern "C" void kernel_launch(void* const* d_in, const int* in_sizes, int n_in,
                              void* d_out, int out_size) {
    const float* x         = (const float*)d_in[0];
    const float* in_proj_w = (const float*)d_in[1];
    const float* conv_w    = (const float*)d_in[2];
    const float* conv_b    = (const float*)d_in[3];
    const float* xproj_w   = (const float*)d_in[4];
    const float* dtw       = (const float*)d_in[5];
    const float* dtb       = (const float*)d_in[6];
    const float* A_logs    = (const float*)d_in[7];
    const float* Ds        = (const float*)d_in[8];
    const float* ln_g      = (const float*)d_in[9];
    const float* ln_b      = (const float*)d_in[10];
    const float* out_w     = (const float*)d_in[11];
    float* out = (float*)d_out;

#define SETA(K, S) cudaFuncSetAttribute(K, cudaFuncAttributeMaxDynamicSharedMemorySize, S)
    SETA(k_dir<0>, SMD); SETA(k_dir<1>, SMD); SETA(k_dir<2>, SMD); SETA(k_dir<3>, SMD);
    SETA(k_dir<4>, SMD); SETA(k_dir<5>, SMD); SETA(k_dir<6>, SMD); SETA(k_dir<7>, SMD);
    SETA(k_final, SM4);
#undef SETA

    k_inproj<<<L_TOT / 24, 256>>>(x, in_proj_w);
    k_conv<<<L_TOT / 4, 512>>>(conv_w, conv_b);

    k_dir<0><<<NCH, 128, SMD>>>(xproj_w, dtw, dtb, A_logs, Ds);
    k_dir<1><<<NCH, 128, SMD>>>(xproj_w, dtw, dtb, A_logs, Ds);
    k_dir<2><<<NCH, 128, SMD>>>(xproj_w, dtw, dtb, A_logs, Ds);
    k_dir<3><<<NCH, 128, SMD>>>(xproj_w, dtw, dtb, A_logs, Ds);
    k_dir<4><<<NCH, 128, SMD>>>(xproj_w, dtw, dtb, A_logs, Ds);
    k_dir<5><<<NCH, 128, SMD>>>(xproj_w, dtw, dtb, A_logs, Ds);
    k_dir<6><<<NCH, 128, SMD>>>(xproj_w, dtw, dtb, A_logs, Ds);
    k_dir<7><<<NCH, 128, SMD>>>(xproj_w, dtw, dtb, A_logs, Ds);

    k_final<<<L_TOT / 16, 128, SM4>>>(ln_g, ln_b, out_w, out);
}

// round 14
// speedup vs baseline: 1.2578x; 1.1356x over previous
#include <cuda_runtime.h>
#include <math.h>

#define L_TOT 13824
#define CL    24
#define NCH   576
#define DM    128
#define NST   16

typedef unsigned long long u64t;

// ---------------- device scratch (static, no allocations) ----------------
__device__ float g_buf[2][L_TOT * DM];   // ping-pong xc buffers [S][128], spatial
__device__ float g_z[L_TOT * DM];        // silu(z)
__device__ float g_xp[L_TOT * DM];       // pre-conv x part
__device__ float g_Ach[NCH * 2048];      // chunk aggregate P, chunk-major
__device__ float g_Bch[NCH * 2048];      // chunk aggregate h_end, chunk-major
__device__ float g_Hpref[NCH * 2048];    // exclusive prefix h0, chunk-major
__device__ volatile unsigned g_barc[16]; // monotonic grid-barrier counters

__device__ __forceinline__ float siluf(float v) { return v / (1.f + __expf(-v)); }
__device__ __forceinline__ float softplusf(float x) {
    if (x > 20.f) return x;
    return __logf(1.f + __expf(x));
}

// f32x2 packed helpers
__device__ __forceinline__ u64t pk2(float lo, float hi) {
    u64t r; asm("mov.b64 %0,{%1,%2};" : "=l"(r) : "f"(lo), "f"(hi)); return r;
}
__device__ __forceinline__ void upk2(u64t v, float& lo, float& hi) {
    asm("mov.b64 {%0,%1},%2;" : "=f"(lo), "=f"(hi) : "l"(v));
}
__device__ __forceinline__ u64t mul2_(u64t a, u64t b) {
    u64t r; asm("mul.rn.f32x2 %0,%1,%2;" : "=l"(r) : "l"(a), "l"(b)); return r;
}
__device__ __forceinline__ u64t fma2_(u64t a, u64t b, u64t c) {
    u64t r; asm("fma.rn.f32x2 %0,%1,%2,%3;" : "=l"(r) : "l"(a), "l"(b), "l"(c)); return r;
}

// runtime seq -> spatial map (flip folded in)
__device__ __forceinline__ int sp_map(int l, int dir) {
    if (dir & 1) l = L_TOT - 1 - l;
    int i0 = l % 24;
    int t  = l / 24;
    int i1 = t % 24;
    int i2 = t / 24;
    int m0, m1, m2;
    switch (dir >> 1) {
        case 0:  m0 = 1;   m1 = 576; m2 = 24;  break;
        case 1:  m0 = 1;   m1 = 24;  m2 = 576; break;
        case 2:  m0 = 576; m1 = 24;  m2 = 1;   break;
        default: m0 = 24;  m1 = 1;   m2 = 576; break;
    }
    return i0 * m0 + i1 * m1 + i2 * m2;
}

// all-576-block barrier; monotonic counter => safe across graph replays
__device__ __forceinline__ void grid_bar(int slot) {
    __syncthreads();
    if (threadIdx.x == 0) {
        __threadfence();
        unsigned old = atomicAdd((unsigned*)(g_barc + slot), 1u);
        unsigned target = old - (old % NCH) + NCH;
        while (g_barc[slot] < target) __nanosleep(32);
        __threadfence();
    }
    __syncthreads();
}

// ---------------- K0: in_proj ----------------
__global__ void __launch_bounds__(256) k_inproj(const float* __restrict__ x,
                                                const float* __restrict__ Win) {
    const int ST = 24;
    __shared__ float xs[ST * DM];
    int s0 = blockIdx.x * ST;
    for (int j = threadIdx.x; j < ST * DM; j += 256) xs[j] = x[s0 * DM + j];
    __syncthreads();
    int e = threadIdx.x;
    float acc[ST];
#pragma unroll
    for (int i = 0; i < ST; i++) acc[i] = 0.f;
    const float4* w4 = (const float4*)(Win + e * DM);
    for (int k4 = 0; k4 < DM / 4; k4++) {
        float4 w = w4[k4];
#pragma unroll
        for (int i = 0; i < ST; i++) {
            float4 xv = *(const float4*)(xs + i * DM + k4 * 4);
            acc[i] = fmaf(w.x, xv.x, fmaf(w.y, xv.y, fmaf(w.z, xv.z, fmaf(w.w, xv.w, acc[i]))));
        }
    }
    if (e < DM) {
#pragma unroll
        for (int i = 0; i < ST; i++) g_xp[(s0 + i) * DM + e] = acc[i];
    } else {
        int c = e - DM;
#pragma unroll
        for (int i = 0; i < ST; i++) g_z[(s0 + i) * DM + c] = siluf(acc[i]);
    }
}

// ---------------- K0b: depthwise conv + silu ----------------
__global__ void __launch_bounds__(512) k_conv(const float* __restrict__ cw,
                                              const float* __restrict__ cb) {
    __shared__ float cws[DM * 27];
    int tid = threadIdx.x;
    for (int j = tid; j < DM * 27; j += 512) cws[j] = cw[j];
    __syncthreads();
    int c = tid & 127;
    int s = blockIdx.x * 4 + (tid >> 7);
    int d0 = s % 24, t = s / 24, w0 = t % 24, h0 = t / 24;
    float acc = cb[c];
#pragma unroll
    for (int kh = 0; kh < 3; kh++) {
        int hh = h0 + kh - 1; if ((unsigned)hh >= 24u) continue;
#pragma unroll
        for (int kw = 0; kw < 3; kw++) {
            int ww = w0 + kw - 1; if ((unsigned)ww >= 24u) continue;
#pragma unroll
            for (int kd = 0; kd < 3; kd++) {
                int dd = d0 + kd - 1; if ((unsigned)dd >= 24u) continue;
                acc = fmaf(cws[c * 27 + kh * 9 + kw * 3 + kd],
                           g_xp[((hh * 24 + ww) * 24 + dd) * DM + c], acc);
            }
        }
    }
    g_buf[0][s * DM + c] = siluf(acc);
}

// ---------------- persistent all-directions kernel -----------------------
// smem layout (floats):
#define SM_BC   0                          // [24*32]  C/B rows, persists all phases
#define SM_U    768                        // [24][132] u tile, l-major (conflict-free)
#define SM_W    (SM_U + 24 * 132)          // [128][41] W transposed (k-major)
#define SM_XD   (SM_W + 128 * 41)          // [40][28]
#define SM_DTW  (SM_XD + 40 * 28)          // [128][9]
#define SM_BIAS (SM_DTW + 128 * 9)         // [128]
#define SM_Q    (SM_BIAS + 128)            // [24] ints
#define SMEM_FLOATS (SM_Q + 24)
// phase2 region (aliases phase1 scratch, starts at 768 => bc_s & q_s preserved)
#define SM_A2   768
#define SM_B2   (768 + NCH * 5)
#define SM_H2   (768 + 2 * NCH * 5)

__global__ void __launch_bounds__(128, 4) k_dirs(const float* __restrict__ xproj_w,
                                                 const float* __restrict__ dtw_g,
                                                 const float* __restrict__ dtb_g,
                                                 const float* __restrict__ Alog_g,
                                                 const float* __restrict__ Ds_g) {
    extern __shared__ float sm[];
    float* bc_s   = sm + SM_BC;
    float* u_s    = sm + SM_U;
    float* W_s    = sm + SM_W;
    float* xd_s   = sm + SM_XD;
    float* dtw_s  = sm + SM_DTW;
    float* bias_s = sm + SM_BIAS;
    int*   q_s    = (int*)(sm + SM_Q);

    const int tid = threadIdx.x;
    const int ci  = blockIdx.x;
    const int L0  = ci * CL;
    int bar = 0;

#pragma unroll 1
    for (int dir = 0; dir < 8; dir++) {
        const float* __restrict__ xin = g_buf[dir & 1];
        float* __restrict__ xout = g_buf[(dir + 1) & 1];

        // ---- phase 1: params + gather u + GEMM + dt/B/C + local scan ----
        if (tid < CL) q_s[tid] = sp_map(L0 + tid, dir);
        for (int j = tid; j < 40 * DM; j += 128) {
            int f = j >> 7, k = j & 127;
            W_s[k * 41 + f] = xproj_w[dir * 40 * DM + j];
        }
        for (int j = tid; j < DM * 8; j += 128)
            dtw_s[(j >> 3) * 9 + (j & 7)] = dtw_g[dir * DM * 8 + j];
        if (tid < DM) bias_s[tid] = dtb_g[dir * DM + tid];
        __syncthreads();

#pragma unroll
        for (int l = 0; l < CL; l++) u_s[l * 132 + tid] = xin[q_s[l] * DM + tid];
        __syncthreads();

        // xd(40x24) = W(40x128) @ u(128x24); 120 threads, 8 l's each
        if (tid < 120) {
            int f = tid % 40, lg = tid / 40, l0 = lg * 8;
            float acc[8];
#pragma unroll
            for (int i = 0; i < 8; i++) acc[i] = 0.f;
#pragma unroll 4
            for (int k4 = 0; k4 < 32; k4++) {
                float w0 = W_s[(4 * k4 + 0) * 41 + f];
                float w1 = W_s[(4 * k4 + 1) * 41 + f];
                float w2 = W_s[(4 * k4 + 2) * 41 + f];
                float w3 = W_s[(4 * k4 + 3) * 41 + f];
#pragma unroll
                for (int i = 0; i < 8; i++) {
                    float4 uv = *(const float4*)(u_s + (l0 + i) * 132 + 4 * k4);
                    acc[i] = fmaf(w0, uv.x, fmaf(w1, uv.y, fmaf(w2, uv.z, fmaf(w3, uv.w, acc[i]))));
                }
            }
#pragma unroll
            for (int i = 0; i < 8; i++) xd_s[f * 28 + l0 + i] = acc[i];
        }
        __syncthreads();
        for (int j = tid; j < CL * 32; j += 128)
            bc_s[j] = xd_s[(8 + (j & 31)) * 28 + (j >> 5)];
        __syncthreads();

        float A_[NST];
        {
            const float4* a4 = (const float4*)(Alog_g + (dir * DM + tid) * NST);
#pragma unroll
            for (int q = 0; q < 4; q++) {
                float4 v = a4[q];
                A_[4 * q]     = -__expf(v.x);
                A_[4 * q + 1] = -__expf(v.y);
                A_[4 * q + 2] = -__expf(v.z);
                A_[4 * q + 3] = -__expf(v.w);
            }
        }
        float A0 = A_[0];
        bool fast = true;
#pragma unroll
        for (int n = 0; n < NST; n++)
            if (fabsf(A_[n] - (float)(n + 1) * A0) > 1e-5f * fabsf(A_[n])) fast = false;
        float Dv = Ds_g[dir * DM + tid];

        float yv[CL], cumv[CL];
        float cum = 0.f;

        if (fast) {
            u64t h2[8];
#pragma unroll
            for (int k = 0; k < 8; k++) h2[k] = 0ull;
#pragma unroll
            for (int g = 0; g < 3; g++) {
                float dtl[8], e1l[8];
#pragma unroll
                for (int j = 0; j < 8; j++) {
                    int l = g * 8 + j;
                    float dtr = bias_s[tid];
#pragma unroll
                    for (int r = 0; r < 8; r++)
                        dtr = fmaf(dtw_s[tid * 9 + r], xd_s[r * 28 + l], dtr);
                    float dt = softplusf(dtr);
                    dtl[j] = dt;
                    e1l[j] = __expf(A0 * dt);
                }
#pragma unroll
                for (int j = 0; j < 8; j++) {
                    int l = g * 8 + j;
                    float u  = u_s[l * 132 + tid];
                    float dt = dtl[j];
                    float e1 = e1l[j];
                    cum += dt; cumv[l] = cum;
                    float e2 = e1 * e1, e4 = e2 * e2, e8 = e4 * e4;
                    u64t e4p = pk2(e4, e4), e8p = pk2(e8, e8);
                    u64t av[8];
                    av[0] = pk2(e1, e2);
                    av[1] = mul2_(av[0], pk2(e2, e2));
                    av[2] = mul2_(av[0], e4p);
                    av[3] = mul2_(av[1], e4p);
                    av[4] = mul2_(av[0], e8p);
                    av[5] = mul2_(av[1], e8p);
                    av[6] = mul2_(av[2], e8p);
                    av[7] = mul2_(av[3], e8p);
                    float dtu = dt * u;
                    u64t dtu2 = pk2(dtu, dtu);
                    const ulonglong2* Bq = (const ulonglong2*)(bc_s + l * 32);
                    u64t ya = 0ull, yb = 0ull;
#pragma unroll
                    for (int q = 0; q < 4; q++) {
                        ulonglong2 bb = Bq[q];
                        h2[2 * q]     = fma2_(av[2 * q],     h2[2 * q],     mul2_(dtu2, bb.x));
                        h2[2 * q + 1] = fma2_(av[2 * q + 1], h2[2 * q + 1], mul2_(dtu2, bb.y));
                    }
#pragma unroll
                    for (int q = 0; q < 4; q++) {
                        ulonglong2 cc = Bq[4 + q];
                        ya = fma2_(h2[2 * q],     cc.x, ya);
                        yb = fma2_(h2[2 * q + 1], cc.y, yb);
                    }
                    u64t ys = fma2_(ya, pk2(1.f, 1.f), yb);
                    float ylo, yhi; upk2(ys, ylo, yhi);
                    yv[l] = fmaf(u, Dv, ylo + yhi);
                }
            }
            float hv[NST];
#pragma unroll
            for (int k = 0; k < 8; k++) upk2(h2[k], hv[2 * k], hv[2 * k + 1]);
            float p1 = __expf(A0 * cum);
            float p2 = p1 * p1, p4 = p2 * p2, p8 = p4 * p4;
            float P[NST];
            P[0] = p1; P[1] = p2; P[2] = p2 * p1; P[3] = p4;
            P[4] = p4 * p1; P[5] = p4 * p2; P[6] = p4 * P[2]; P[7] = p8;
            P[8] = p8 * p1; P[9] = p8 * p2; P[10] = p8 * P[2]; P[11] = p8 * p4;
            P[12] = p8 * P[4]; P[13] = p8 * P[5]; P[14] = p8 * P[6]; P[15] = p8 * p8;
            float4* pa = (float4*)(g_Ach + ci * 2048 + tid * 16);
            float4* pb = (float4*)(g_Bch + ci * 2048 + tid * 16);
#pragma unroll
            for (int q = 0; q < 4; q++) {
                pa[q] = make_float4(P[4 * q], P[4 * q + 1], P[4 * q + 2], P[4 * q + 3]);
                pb[q] = make_float4(hv[4 * q], hv[4 * q + 1], hv[4 * q + 2], hv[4 * q + 3]);
            }
        } else {
            float h[NST];
#pragma unroll
            for (int n = 0; n < NST; n++) h[n] = 0.f;
#pragma unroll
            for (int l = 0; l < CL; l++) {
                float u = u_s[l * 132 + tid];
                float dtr = bias_s[tid];
#pragma unroll
                for (int r = 0; r < 8; r++) dtr = fmaf(dtw_s[tid * 9 + r], xd_s[r * 28 + l], dtr);
                float dt = softplusf(dtr);
                cum += dt; cumv[l] = cum;
                float dtu = dt * u;
                float y = u * Dv;
#pragma unroll
                for (int n = 0; n < NST; n++) {
                    h[n] = fmaf(__expf(A_[n] * dt), h[n], dtu * bc_s[l * 32 + n]);
                    y = fmaf(h[n], bc_s[l * 32 + 16 + n], y);
                }
                yv[l] = y;
            }
            float P[NST];
#pragma unroll
            for (int n = 0; n < NST; n++) P[n] = __expf(A_[n] * cum);
            float4* pa = (float4*)(g_Ach + ci * 2048 + tid * 16);
            float4* pb = (float4*)(g_Bch + ci * 2048 + tid * 16);
#pragma unroll
            for (int q = 0; q < 4; q++) {
                pa[q] = make_float4(P[4 * q], P[4 * q + 1], P[4 * q + 2], P[4 * q + 3]);
                pb[q] = make_float4(h[4 * q], h[4 * q + 1], h[4 * q + 2], h[4 * q + 3]);
            }
        }

        grid_bar(bar & 15); bar++;

        // ---- phase 2: exclusive prefix over 576 chunks (blocks 0..511) ----
        if (ci < 512) {
            float* A2 = sm + SM_A2;
            float* B2 = sm + SM_B2;
            float* H2 = sm + SM_H2;
            const int gw0 = ci * 4;
            for (int j = tid; j < NCH * 4; j += 128) {
                int c = j >> 2, w = j & 3;
                A2[c * 5 + w] = g_Ach[c * 2048 + gw0 + w];
                B2[c * 5 + w] = g_Bch[c * 2048 + gw0 + w];
            }
            __syncthreads();
            int w = tid >> 5, lane = tid & 31;
            const int PT = NCH / 32;     // 18
            float Ag = 1.f, Bg = 0.f;
            int c0 = lane * PT;
            for (int k = 0; k < PT; k++) {
                float a = A2[(c0 + k) * 5 + w];
                float b = B2[(c0 + k) * 5 + w];
                Bg = fmaf(a, Bg, b);
                Ag *= a;
            }
#pragma unroll
            for (int d = 1; d < 32; d <<= 1) {
                float aL = __shfl_up_sync(0xffffffffu, Ag, d);
                float bL = __shfl_up_sync(0xffffffffu, Bg, d);
                if (lane >= d) { Bg = fmaf(Ag, bL, Bg); Ag *= aL; }
            }
            float hp = __shfl_up_sync(0xffffffffu, Bg, 1);
            float h = (lane == 0) ? 0.f : hp;
            for (int k = 0; k < PT; k++) {
                H2[(c0 + k) * 5 + w] = h;
                h = fmaf(A2[(c0 + k) * 5 + w], h, B2[(c0 + k) * 5 + w]);
            }
            __syncthreads();
            for (int j = tid; j < NCH * 4; j += 128) {
                int c = j >> 2, w2 = j & 3;
                g_Hpref[c * 2048 + gw0 + w2] = H2[c * 5 + w2];
            }
        }

        grid_bar(bar & 15); bar++;

        // ---- phase 3: closed-form correction + scatter to spatial ----
        float h0[NST];
        {
            const float4* hp4 = (const float4*)(g_Hpref + ci * 2048 + tid * 16);
#pragma unroll
            for (int q = 0; q < 4; q++) {
                float4 v = hp4[q];
                h0[4 * q] = v.x; h0[4 * q + 1] = v.y; h0[4 * q + 2] = v.z; h0[4 * q + 3] = v.w;
            }
        }
        if (fast) {
            u64t h0p[8];
#pragma unroll
            for (int k = 0; k < 8; k++) h0p[k] = pk2(h0[2 * k], h0[2 * k + 1]);
#pragma unroll
            for (int l = 0; l < CL; l++) {
                float e1 = __expf(A0 * cumv[l]);
                float e2 = e1 * e1, e4 = e2 * e2, e8 = e4 * e4;
                u64t e4p = pk2(e4, e4), e8p = pk2(e8, e8);
                u64t av[8];
                av[0] = pk2(e1, e2);
                av[1] = mul2_(av[0], pk2(e2, e2));
                av[2] = mul2_(av[0], e4p);
                av[3] = mul2_(av[1], e4p);
                av[4] = mul2_(av[0], e8p);
                av[5] = mul2_(av[1], e8p);
                av[6] = mul2_(av[2], e8p);
                av[7] = mul2_(av[3], e8p);
                const ulonglong2* Cq = (const ulonglong2*)(bc_s + l * 32 + 16);
                u64t acc = 0ull;
#pragma unroll
                for (int q = 0; q < 4; q++) {
                    ulonglong2 cc = Cq[q];
                    acc = fma2_(mul2_(h0p[2 * q],     av[2 * q]),     cc.x, acc);
                    acc = fma2_(mul2_(h0p[2 * q + 1], av[2 * q + 1]), cc.y, acc);
                }
                float lo, hi; upk2(acc, lo, hi);
                xout[q_s[l] * DM + tid] = yv[l] + lo + hi;
            }
        } else {
#pragma unroll
            for (int l = 0; l < CL; l++) {
                float y = yv[l];
#pragma unroll
                for (int n = 0; n < NST; n++)
                    y = fmaf(h0[n] * __expf(A_[n] * cumv[l]), bc_s[l * 32 + 16 + n], y);
                xout[q_s[l] * DM + tid] = y;
            }
        }

        grid_bar(bar & 15); bar++;
    }
}

// ---------------- K4: LayerNorm + gate + out_proj ------------------------
__global__ void __launch_bounds__(128) k_final(const float* __restrict__ gamma,
                                               const float* __restrict__ beta,
                                               const float* __restrict__ Wout,
                                               float* __restrict__ out) {
    extern __shared__ float sm[];
    float* ym = sm;                   // [16][132]
    float* Wt = sm + 16 * 132;        // [128][129]
    __shared__ float mu_s[16], rs_s[16];
    const int tid = threadIdx.x;
    const int s0 = blockIdx.x * 16;

    for (int j = tid; j < 16 * DM; j += 128) {
        int si = j >> 7, c = j & 127;
        ym[si * 132 + c] = g_buf[0][(s0 + si) * DM + c];
    }
    for (int j = tid; j < DM * DM; j += 128) {
        int c = j >> 7, e = j & 127;
        Wt[e * 129 + c] = Wout[j];
    }
    __syncthreads();

    if (tid < 16) {
        float m = 0.f;
        for (int c = 0; c < DM; c++) m += ym[tid * 132 + c];
        m *= (1.f / DM);
        float v = 0.f;
        for (int c = 0; c < DM; c++) { float d = ym[tid * 132 + c] - m; v = fmaf(d, d, v); }
        v *= (1.f / DM);
        mu_s[tid] = m;
        rs_s[tid] = rsqrtf(v + 1e-5f);
    }
    __syncthreads();

    for (int j = tid; j < 16 * DM; j += 128) {
        int si = j >> 7, c = j & 127;
        float v = (ym[si * 132 + c] - mu_s[si]) * rs_s[si] * gamma[c] + beta[c];
        ym[si * 132 + c] = v * g_z[(s0 + si) * DM + c];
    }
    __syncthreads();

    float acc[16];
#pragma unroll
    for (int i = 0; i < 16; i++) acc[i] = 0.f;
    for (int e4 = 0; e4 < DM / 4; e4++) {
        float w0 = Wt[(e4 * 4 + 0) * 129 + tid];
        float w1 = Wt[(e4 * 4 + 1) * 129 + tid];
        float w2 = Wt[(e4 * 4 + 2) * 129 + tid];
        float w3 = Wt[(e4 * 4 + 3) * 129 + tid];
#pragma unroll
        for (int si = 0; si < 16; si++) {
            float4 yv = *(const float4*)(ym + si * 132 + e4 * 4);
            acc[si] = fmaf(w0, yv.x, fmaf(w1, yv.y, fmaf(w2, yv.z, fmaf(w3, yv.w, acc[si]))));
        }
    }
#pragma unroll
    for (int si = 0; si < 16; si++) out[(s0 + si) * DM + tid] = acc[si];
}

// ---------------- launch ----------------
#define SMD (SMEM_FLOATS * 4)
#define SM4 ((16 * 132 + 128 * 129) * 4)

extern "C" void kernel_launch(void* const* d_in, const int* in_sizes, int n_in,
                              void* d_out, int out_size) {
    const float* x         = (const float*)d_in[0];
    const float* in_proj_w = (const float*)d_in[1];
    const float* conv_w    = (const float*)d_in[2];
    const float* conv_b    = (const float*)d_in[3];
    const float* xproj_w   = (const float*)d_in[4];
    const float* dtw       = (const float*)d_in[5];
    const float* dtb       = (const float*)d_in[6];
    const float* A_logs    = (const float*)d_in[7];
    const float* Ds        = (const float*)d_in[8];
    const float* ln_g      = (const float*)d_in[9];
    const float* ln_b      = (const float*)d_in[10];
    const float* out_w     = (const float*)d_in[11];
    float* out = (float*)d_out;

    cudaFuncSetAttribute(k_dirs,  cudaFuncAttributeMaxDynamicSharedMemorySize, SMD);
    cudaFuncSetAttribute(k_final, cudaFuncAttributeMaxDynamicSharedMemorySize, SM4);

    k_inproj<<<L_TOT / 24, 256>>>(x, in_proj_w);
    k_conv<<<L_TOT / 4, 512>>>(conv_w, conv_b);

    k_dirs<<<NCH, 128, SMD>>>(xproj_w, dtw, dtb, A_logs, Ds);

    k_final<<<L_TOT / 16, 128, SM4>>>(ln_g, ln_b, out_w, out);
}

// round 15
// speedup vs baseline: 1.2669x; 1.0072x over previous
#include <cuda_runtime.h>
#include <math.h>

#define L_TOT 13824
#define CL    24
#define NCH   576
#define DM    128
#define NST   16

typedef unsigned long long u64t;

// ---------------- device scratch (static, no allocations) ----------------
__device__ float g_buf[2][L_TOT * DM];   // ping-pong xc buffers [S][128], spatial
__device__ float g_z[L_TOT * DM];        // silu(z)
__device__ float g_xp[L_TOT * DM];       // pre-conv x part
__device__ float g_Ach[NCH * 2048];      // chunk aggregate P, chunk-major
__device__ float g_Bch[NCH * 2048];      // chunk aggregate h_end, chunk-major
__device__ float g_Hpref[NCH * 2048];    // exclusive prefix h0, chunk-major
__device__ volatile unsigned g_barc[16]; // monotonic grid-barrier counters

__device__ __forceinline__ float siluf(float v) { return v / (1.f + __expf(-v)); }
__device__ __forceinline__ float softplusf(float x) {
    if (x > 20.f) return x;
    return __logf(1.f + __expf(x));
}

// f32x2 packed helpers
__device__ __forceinline__ u64t pk2(float lo, float hi) {
    u64t r; asm("mov.b64 %0,{%1,%2};" : "=l"(r) : "f"(lo), "f"(hi)); return r;
}
__device__ __forceinline__ void upk2(u64t v, float& lo, float& hi) {
    asm("mov.b64 {%0,%1},%2;" : "=f"(lo), "=f"(hi) : "l"(v));
}
__device__ __forceinline__ u64t mul2_(u64t a, u64t b) {
    u64t r; asm("mul.rn.f32x2 %0,%1,%2;" : "=l"(r) : "l"(a), "l"(b)); return r;
}
__device__ __forceinline__ u64t fma2_(u64t a, u64t b, u64t c) {
    u64t r; asm("fma.rn.f32x2 %0,%1,%2,%3;" : "=l"(r) : "l"(a), "l"(b), "l"(c)); return r;
}

// runtime seq -> spatial map (flip folded in)
__device__ __forceinline__ int sp_map(int l, int dir) {
    if (dir & 1) l = L_TOT - 1 - l;
    int i0 = l % 24;
    int t  = l / 24;
    int i1 = t % 24;
    int i2 = t / 24;
    int m0, m1, m2;
    switch (dir >> 1) {
        case 0:  m0 = 1;   m1 = 576; m2 = 24;  break;
        case 1:  m0 = 1;   m1 = 24;  m2 = 576; break;
        case 2:  m0 = 576; m1 = 24;  m2 = 1;   break;
        default: m0 = 24;  m1 = 1;   m2 = 576; break;
    }
    return i0 * m0 + i1 * m1 + i2 * m2;
}

// all-576-block barrier; monotonic counter => safe across graph replays
__device__ __forceinline__ void grid_bar(int slot) {
    __syncthreads();
    if (threadIdx.x == 0) {
        __threadfence();
        unsigned old = atomicAdd((unsigned*)(g_barc + slot), 1u);
        unsigned target = old - (old % NCH) + NCH;
        while (g_barc[slot] < target) __nanosleep(32);
        __threadfence();
    }
    __syncthreads();
}

// ---------------- K0: in_proj ----------------
__global__ void __launch_bounds__(256) k_inproj(const float* __restrict__ x,
                                                const float* __restrict__ Win) {
    const int ST = 24;
    __shared__ float xs[ST * DM];
    int s0 = blockIdx.x * ST;
    for (int j = threadIdx.x; j < ST * DM; j += 256) xs[j] = x[s0 * DM + j];
    __syncthreads();
    int e = threadIdx.x;
    float acc[ST];
#pragma unroll
    for (int i = 0; i < ST; i++) acc[i] = 0.f;
    const float4* w4 = (const float4*)(Win + e * DM);
    for (int k4 = 0; k4 < DM / 4; k4++) {
        float4 w = w4[k4];
#pragma unroll
        for (int i = 0; i < ST; i++) {
            float4 xv = *(const float4*)(xs + i * DM + k4 * 4);
            acc[i] = fmaf(w.x, xv.x, fmaf(w.y, xv.y, fmaf(w.z, xv.z, fmaf(w.w, xv.w, acc[i]))));
        }
    }
    if (e < DM) {
#pragma unroll
        for (int i = 0; i < ST; i++) g_xp[(s0 + i) * DM + e] = acc[i];
    } else {
        int c = e - DM;
#pragma unroll
        for (int i = 0; i < ST; i++) g_z[(s0 + i) * DM + c] = siluf(acc[i]);
    }
}

// ---------------- K0b: depthwise conv + silu ----------------
__global__ void __launch_bounds__(512) k_conv(const float* __restrict__ cw,
                                              const float* __restrict__ cb) {
    __shared__ float cws[DM * 27];
    int tid = threadIdx.x;
    for (int j = tid; j < DM * 27; j += 512) cws[j] = cw[j];
    __syncthreads();
    int c = tid & 127;
    int s = blockIdx.x * 4 + (tid >> 7);
    int d0 = s % 24, t = s / 24, w0 = t % 24, h0 = t / 24;
    float acc = cb[c];
#pragma unroll
    for (int kh = 0; kh < 3; kh++) {
        int hh = h0 + kh - 1; if ((unsigned)hh >= 24u) continue;
#pragma unroll
        for (int kw = 0; kw < 3; kw++) {
            int ww = w0 + kw - 1; if ((unsigned)ww >= 24u) continue;
#pragma unroll
            for (int kd = 0; kd < 3; kd++) {
                int dd = d0 + kd - 1; if ((unsigned)dd >= 24u) continue;
                acc = fmaf(cws[c * 27 + kh * 9 + kw * 3 + kd],
                           g_xp[((hh * 24 + ww) * 24 + dd) * DM + c], acc);
            }
        }
    }
    g_buf[0][s * DM + c] = siluf(acc);
}

// ---------------- persistent all-directions kernel -----------------------
// smem layout (floats):
#define SM_BC   0                          // [24*32]  C/B rows, persists all phases
#define SM_U    768                        // [24][132] u tile, l-major (conflict-free)
#define SM_W    (SM_U + 24 * 132)          // [128][41] W transposed (k-major)
#define SM_XD   (SM_W + 128 * 41)          // [40][28]
#define SM_DTW  (SM_XD + 40 * 28)          // [128][9]
#define SM_BIAS (SM_DTW + 128 * 9)         // [128]
#define SM_Q    (SM_BIAS + 128)            // [24] ints
#define SMEM_FLOATS (SM_Q + 24)
// phase2 region (aliases phase1 scratch, starts at 768 => bc_s & q_s preserved)
#define SM_A2   768
#define SM_B2   (768 + NCH * 5)
#define SM_H2   (768 + 2 * NCH * 5)

__global__ void __launch_bounds__(128, 4) k_dirs(const float* __restrict__ xproj_w,
                                                 const float* __restrict__ dtw_g,
                                                 const float* __restrict__ dtb_g,
                                                 const float* __restrict__ Alog_g,
                                                 const float* __restrict__ Ds_g) {
    extern __shared__ float sm[];
    float* bc_s   = sm + SM_BC;
    float* u_s    = sm + SM_U;
    float* W_s    = sm + SM_W;
    float* xd_s   = sm + SM_XD;
    float* dtw_s  = sm + SM_DTW;
    float* bias_s = sm + SM_BIAS;
    int*   q_s    = (int*)(sm + SM_Q);

    const int tid = threadIdx.x;
    const int ci  = blockIdx.x;
    const int L0  = ci * CL;
    int bar = 0;

#pragma unroll 1
    for (int dir = 0; dir < 8; dir++) {
        const float* __restrict__ xin = g_buf[dir & 1];
        float* __restrict__ xout = g_buf[(dir + 1) & 1];

        // ---- phase 1: params + gather u + GEMM + dt/B/C + local scan ----
        if (tid < CL) q_s[tid] = sp_map(L0 + tid, dir);
        for (int j = tid; j < 40 * DM; j += 128) {
            int f = j >> 7, k = j & 127;
            W_s[k * 41 + f] = xproj_w[dir * 40 * DM + j];
        }
        for (int j = tid; j < DM * 8; j += 128)
            dtw_s[(j >> 3) * 9 + (j & 7)] = dtw_g[dir * DM * 8 + j];
        if (tid < DM) bias_s[tid] = dtb_g[dir * DM + tid];
        __syncthreads();

#pragma unroll
        for (int l = 0; l < CL; l++) u_s[l * 132 + tid] = xin[q_s[l] * DM + tid];
        __syncthreads();

        // xd(40x24) = W(40x128) @ u(128x24); 120 threads, 8 l's each
        if (tid < 120) {
            int f = tid % 40, lg = tid / 40, l0 = lg * 8;
            float acc[8];
#pragma unroll
            for (int i = 0; i < 8; i++) acc[i] = 0.f;
#pragma unroll 4
            for (int k4 = 0; k4 < 32; k4++) {
                float w0 = W_s[(4 * k4 + 0) * 41 + f];
                float w1 = W_s[(4 * k4 + 1) * 41 + f];
                float w2 = W_s[(4 * k4 + 2) * 41 + f];
                float w3 = W_s[(4 * k4 + 3) * 41 + f];
#pragma unroll
                for (int i = 0; i < 8; i++) {
                    float4 uv = *(const float4*)(u_s + (l0 + i) * 132 + 4 * k4);
                    acc[i] = fmaf(w0, uv.x, fmaf(w1, uv.y, fmaf(w2, uv.z, fmaf(w3, uv.w, acc[i]))));
                }
            }
#pragma unroll
            for (int i = 0; i < 8; i++) xd_s[f * 28 + l0 + i] = acc[i];
        }
        __syncthreads();
        for (int j = tid; j < CL * 32; j += 128)
            bc_s[j] = xd_s[(8 + (j & 31)) * 28 + (j >> 5)];
        __syncthreads();

        float A_[NST];
        {
            const float4* a4 = (const float4*)(Alog_g + (dir * DM + tid) * NST);
#pragma unroll
            for (int q = 0; q < 4; q++) {
                float4 v = a4[q];
                A_[4 * q]     = -__expf(v.x);
                A_[4 * q + 1] = -__expf(v.y);
                A_[4 * q + 2] = -__expf(v.z);
                A_[4 * q + 3] = -__expf(v.w);
            }
        }
        float A0 = A_[0];
        bool fast = true;
#pragma unroll
        for (int n = 0; n < NST; n++)
            if (fabsf(A_[n] - (float)(n + 1) * A0) > 1e-5f * fabsf(A_[n])) fast = false;
        float Dv = Ds_g[dir * DM + tid];

        float yv[CL], cumv[CL];
        float cum = 0.f;

        if (fast) {
            u64t h2[8];
#pragma unroll
            for (int k = 0; k < 8; k++) h2[k] = 0ull;
#pragma unroll
            for (int g = 0; g < 3; g++) {
                float dtl[8], e1l[8];
#pragma unroll
                for (int j = 0; j < 8; j++) {
                    int l = g * 8 + j;
                    float dtr = bias_s[tid];
#pragma unroll
                    for (int r = 0; r < 8; r++)
                        dtr = fmaf(dtw_s[tid * 9 + r], xd_s[r * 28 + l], dtr);
                    float dt = softplusf(dtr);
                    dtl[j] = dt;
                    e1l[j] = __expf(A0 * dt);
                }
#pragma unroll
                for (int j = 0; j < 8; j++) {
                    int l = g * 8 + j;
                    float u  = u_s[l * 132 + tid];
                    float dt = dtl[j];
                    float e1 = e1l[j];
                    cum += dt; cumv[l] = cum;
                    float e2 = e1 * e1, e4 = e2 * e2, e8 = e4 * e4;
                    u64t e4p = pk2(e4, e4), e8p = pk2(e8, e8);
                    u64t av[8];
                    av[0] = pk2(e1, e2);
                    av[1] = mul2_(av[0], pk2(e2, e2));
                    av[2] = mul2_(av[0], e4p);
                    av[3] = mul2_(av[1], e4p);
                    av[4] = mul2_(av[0], e8p);
                    av[5] = mul2_(av[1], e8p);
                    av[6] = mul2_(av[2], e8p);
                    av[7] = mul2_(av[3], e8p);
                    float dtu = dt * u;
                    u64t dtu2 = pk2(dtu, dtu);
                    const ulonglong2* Bq = (const ulonglong2*)(bc_s + l * 32);
                    u64t ya = 0ull, yb = 0ull;
#pragma unroll
                    for (int q = 0; q < 4; q++) {
                        ulonglong2 bb = Bq[q];
                        h2[2 * q]     = fma2_(av[2 * q],     h2[2 * q],     mul2_(dtu2, bb.x));
                        h2[2 * q + 1] = fma2_(av[2 * q + 1], h2[2 * q + 1], mul2_(dtu2, bb.y));
                    }
#pragma unroll
                    for (int q = 0; q < 4; q++) {
                        ulonglong2 cc = Bq[4 + q];
                        ya = fma2_(h2[2 * q],     cc.x, ya);
                        yb = fma2_(h2[2 * q + 1], cc.y, yb);
                    }
                    u64t ys = fma2_(ya, pk2(1.f, 1.f), yb);
                    float ylo, yhi; upk2(ys, ylo, yhi);
                    yv[l] = fmaf(u, Dv, ylo + yhi);
                }
            }
            float hv[NST];
#pragma unroll
            for (int k = 0; k < 8; k++) upk2(h2[k], hv[2 * k], hv[2 * k + 1]);
            float p1 = __expf(A0 * cum);
            float p2 = p1 * p1, p4 = p2 * p2, p8 = p4 * p4;
            float P[NST];
            P[0] = p1; P[1] = p2; P[2] = p2 * p1; P[3] = p4;
            P[4] = p4 * p1; P[5] = p4 * p2; P[6] = p4 * P[2]; P[7] = p8;
            P[8] = p8 * p1; P[9] = p8 * p2; P[10] = p8 * P[2]; P[11] = p8 * p4;
            P[12] = p8 * P[4]; P[13] = p8 * P[5]; P[14] = p8 * P[6]; P[15] = p8 * p8;
            float4* pa = (float4*)(g_Ach + ci * 2048 + tid * 16);
            float4* pb = (float4*)(g_Bch + ci * 2048 + tid * 16);
#pragma unroll
            for (int q = 0; q < 4; q++) {
                pa[q] = make_float4(P[4 * q], P[4 * q + 1], P[4 * q + 2], P[4 * q + 3]);
                pb[q] = make_float4(hv[4 * q], hv[4 * q + 1], hv[4 * q + 2], hv[4 * q + 3]);
            }
        } else {
            float h[NST];
#pragma unroll
            for (int n = 0; n < NST; n++) h[n] = 0.f;
#pragma unroll
            for (int l = 0; l < CL; l++) {
                float u = u_s[l * 132 + tid];
                float dtr = bias_s[tid];
#pragma unroll
                for (int r = 0; r < 8; r++) dtr = fmaf(dtw_s[tid * 9 + r], xd_s[r * 28 + l], dtr);
                float dt = softplusf(dtr);
                cum += dt; cumv[l] = cum;
                float dtu = dt * u;
                float y = u * Dv;
#pragma unroll
                for (int n = 0; n < NST; n++) {
                    h[n] = fmaf(__expf(A_[n] * dt), h[n], dtu * bc_s[l * 32 + n]);
                    y = fmaf(h[n], bc_s[l * 32 + 16 + n], y);
                }
                yv[l] = y;
            }
            float P[NST];
#pragma unroll
            for (int n = 0; n < NST; n++) P[n] = __expf(A_[n] * cum);
            float4* pa = (float4*)(g_Ach + ci * 2048 + tid * 16);
            float4* pb = (float4*)(g_Bch + ci * 2048 + tid * 16);
#pragma unroll
            for (int q = 0; q < 4; q++) {
                pa[q] = make_float4(P[4 * q], P[4 * q + 1], P[4 * q + 2], P[4 * q + 3]);
                pb[q] = make_float4(h[4 * q], h[4 * q + 1], h[4 * q + 2], h[4 * q + 3]);
            }
        }

        grid_bar(bar & 15); bar++;

        // ---- phase 2: exclusive prefix over 576 chunks (blocks 0..511) ----
        if (ci < 512) {
            float* A2 = sm + SM_A2;
            float* B2 = sm + SM_B2;
            float* H2 = sm + SM_H2;
            const int gw0 = ci * 4;
            for (int j = tid; j < NCH * 4; j += 128) {
                int c = j >> 2, w = j & 3;
                A2[c * 5 + w] = g_Ach[c * 2048 + gw0 + w];
                B2[c * 5 + w] = g_Bch[c * 2048 + gw0 + w];
            }
            __syncthreads();
            int w = tid >> 5, lane = tid & 31;
            const int PT = NCH / 32;     // 18
            float Ag = 1.f, Bg = 0.f;
            int c0 = lane * PT;
            for (int k = 0; k < PT; k++) {
                float a = A2[(c0 + k) * 5 + w];
                float b = B2[(c0 + k) * 5 + w];
                Bg = fmaf(a, Bg, b);
                Ag *= a;
            }
#pragma unroll
            for (int d = 1; d < 32; d <<= 1) {
                float aL = __shfl_up_sync(0xffffffffu, Ag, d);
                float bL = __shfl_up_sync(0xffffffffu, Bg, d);
                if (lane >= d) { Bg = fmaf(Ag, bL, Bg); Ag *= aL; }
            }
            float hp = __shfl_up_sync(0xffffffffu, Bg, 1);
            float h = (lane == 0) ? 0.f : hp;
            for (int k = 0; k < PT; k++) {
                H2[(c0 + k) * 5 + w] = h;
                h = fmaf(A2[(c0 + k) * 5 + w], h, B2[(c0 + k) * 5 + w]);
            }
            __syncthreads();
            for (int j = tid; j < NCH * 4; j += 128) {
                int c = j >> 2, w2 = j & 3;
                g_Hpref[c * 2048 + gw0 + w2] = H2[c * 5 + w2];
            }
        }

        grid_bar(bar & 15); bar++;

        // ---- phase 3: closed-form correction + scatter to spatial ----
        float h0[NST];
        {
            const float4* hp4 = (const float4*)(g_Hpref + ci * 2048 + tid * 16);
#pragma unroll
            for (int q = 0; q < 4; q++) {
                float4 v = hp4[q];
                h0[4 * q] = v.x; h0[4 * q + 1] = v.y; h0[4 * q + 2] = v.z; h0[4 * q + 3] = v.w;
            }
        }
        if (fast) {
            u64t h0p[8];
#pragma unroll
            for (int k = 0; k < 8; k++) h0p[k] = pk2(h0[2 * k], h0[2 * k + 1]);
#pragma unroll
            for (int l = 0; l < CL; l++) {
                float e1 = __expf(A0 * cumv[l]);
                float e2 = e1 * e1, e4 = e2 * e2, e8 = e4 * e4;
                u64t e4p = pk2(e4, e4), e8p = pk2(e8, e8);
                u64t av[8];
                av[0] = pk2(e1, e2);
                av[1] = mul2_(av[0], pk2(e2, e2));
                av[2] = mul2_(av[0], e4p);
                av[3] = mul2_(av[1], e4p);
                av[4] = mul2_(av[0], e8p);
                av[5] = mul2_(av[1], e8p);
                av[6] = mul2_(av[2], e8p);
                av[7] = mul2_(av[3], e8p);
                const ulonglong2* Cq = (const ulonglong2*)(bc_s + l * 32 + 16);
                u64t acc = 0ull;
#pragma unroll
                for (int q = 0; q < 4; q++) {
                    ulonglong2 cc = Cq[q];
                    acc = fma2_(mul2_(h0p[2 * q],     av[2 * q]),     cc.x, acc);
                    acc = fma2_(mul2_(h0p[2 * q + 1], av[2 * q + 1]), cc.y, acc);
                }
                float lo, hi; upk2(acc, lo, hi);
                xout[q_s[l] * DM + tid] = yv[l] + lo + hi;
            }
        } else {
#pragma unroll
            for (int l = 0; l < CL; l++) {
                float y = yv[l];
#pragma unroll
                for (int n = 0; n < NST; n++)
                    y = fmaf(h0[n] * __expf(A_[n] * cumv[l]), bc_s[l * 32 + 16 + n], y);
                xout[q_s[l] * DM + tid] = y;
            }
        }

        grid_bar(bar & 15); bar++;
    }
}

// ---------------- K4: LayerNorm + gate + out_proj (rewritten) ------------
// 32 rows/block, 256 threads. LN: 8 thr/row shfl reduce. GEMM: 128 cols x 2
// row-halves, Wout read directly from global (L1-resident), ym broadcast LDS.
__global__ void __launch_bounds__(256) k_final(const float* __restrict__ gamma,
                                               const float* __restrict__ beta,
                                               const float* __restrict__ Wout,
                                               float* __restrict__ out) {
    __shared__ float ym[32 * 132];
    const int tid = threadIdx.x;
    const int s0 = blockIdx.x * 32;

    for (int j = tid; j < 32 * DM; j += 256) {
        int si = j >> 7, c = j & 127;
        ym[si * 132 + c] = g_buf[0][(s0 + si) * DM + c];
    }
    __syncthreads();

    // LN stats: row = tid>>3 (0..31), 8 threads per row, 16 elems each
    {
        int row = tid >> 3;
        int sub = tid & 7;
        int c0 = sub * 16;
        float s = 0.f;
#pragma unroll
        for (int c = 0; c < 16; c++) s += ym[row * 132 + c0 + c];
#pragma unroll
        for (int d = 4; d; d >>= 1) s += __shfl_down_sync(0xffffffffu, s, d, 8);
        float m = __shfl_sync(0xffffffffu, s, 0, 8) * (1.f / DM);
        float v = 0.f;
#pragma unroll
        for (int c = 0; c < 16; c++) {
            float dcv = ym[row * 132 + c0 + c] - m;
            v = fmaf(dcv, dcv, v);
        }
#pragma unroll
        for (int d = 4; d; d >>= 1) v += __shfl_down_sync(0xffffffffu, v, d, 8);
        float r = rsqrtf(__shfl_sync(0xffffffffu, v, 0, 8) * (1.f / DM) + 1e-5f);
        // normalize + gamma/beta + gate, in place
#pragma unroll
        for (int c = 0; c < 16; c++) {
            int cc = c0 + c;
            float val = (ym[row * 132 + cc] - m) * r * gamma[cc] + beta[cc];
            ym[row * 132 + cc] = val * g_z[(s0 + row) * DM + cc];
        }
    }
    __syncthreads();

    // GEMM: out[32 x 128] = ym @ Wout^T; thread = (e, row-half)
    {
        int e  = tid & 127;
        int rh = tid >> 7;           // 0 or 1 -> rows rh*16 .. rh*16+15
        float acc[16];
#pragma unroll
        for (int i = 0; i < 16; i++) acc[i] = 0.f;
        const float4* w4 = (const float4*)(Wout + e * DM);
        for (int k4 = 0; k4 < DM / 4; k4++) {
            float4 w = w4[k4];
#pragma unroll
            for (int i = 0; i < 16; i++) {
                float4 yv = *(const float4*)(ym + (rh * 16 + i) * 132 + k4 * 4);
                acc[i] = fmaf(w.x, yv.x, fmaf(w.y, yv.y, fmaf(w.z, yv.z, fmaf(w.w, yv.w, acc[i]))));
            }
        }
#pragma unroll
        for (int i = 0; i < 16; i++)
            out[(s0 + rh * 16 + i) * DM + e] = acc[i];
    }
}

// ---------------- launch ----------------
#define SMD (SMEM_FLOATS * 4)

extern "C" void kernel_launch(void* const* d_in, const int* in_sizes, int n_in,
                              void* d_out, int out_size) {
    const float* x         = (const float*)d_in[0];
    const float* in_proj_w = (const float*)d_in[1];
    const float* conv_w    = (const float*)d_in[2];
    const float* conv_b    = (const float*)d_in[3];
    const float* xproj_w   = (const float*)d_in[4];
    const float* dtw       = (const float*)d_in[5];
    const float* dtb       = (const float*)d_in[6];
    const float* A_logs    = (const float*)d_in[7];
    const float* Ds        = (const float*)d_in[8];
    const float* ln_g      = (const float*)d_in[9];
    const float* ln_b      = (const float*)d_in[10];
    const float* out_w     = (const float*)d_in[11];
    float* out = (float*)d_out;

    cudaFuncSetAttribute(k_dirs, cudaFuncAttributeMaxDynamicSharedMemorySize, SMD);

    k_inproj<<<L_TOT / 24, 256>>>(x, in_proj_w);
    k_conv<<<L_TOT / 4, 512>>>(conv_w, conv_b);

    k_dirs<<<NCH, 128, SMD>>>(xproj_w, dtw, dtb, A_logs, Ds);

    k_final<<<L_TOT / 32, 256>>>(ln_g, ln_b, out_w, out);
}

// round 16
// speedup vs baseline: 1.3329x; 1.0521x over previous
#include <cuda_runtime.h>
#include <math.h>

#define L_TOT 13824
#define CL    24
#define NCH   576
#define DM    128
#define NST   16

typedef unsigned long long u64t;

// ---------------- device scratch (static, no allocations) ----------------
__device__ float g_buf[2][L_TOT * DM];   // ping-pong xc buffers [S][128], spatial
__device__ float g_z[L_TOT * DM];        // silu(z)
__device__ float g_xp[L_TOT * DM];       // pre-conv x part
__device__ float g_Ach[NCH * 2048];      // chunk aggregate P, chunk-major
__device__ float g_Bch[NCH * 2048];      // chunk aggregate h_end, chunk-major
__device__ float g_Hpref[NCH * 2048];    // exclusive prefix h0, chunk-major
__device__ volatile unsigned g_barc[16]; // monotonic grid-barrier counters

__device__ __forceinline__ float siluf(float v) { return v / (1.f + __expf(-v)); }
__device__ __forceinline__ float softplusf(float x) {
    if (x > 20.f) return x;
    return __logf(1.f + __expf(x));
}

// f32x2 packed helpers
__device__ __forceinline__ u64t pk2(float lo, float hi) {
    u64t r; asm("mov.b64 %0,{%1,%2};" : "=l"(r) : "f"(lo), "f"(hi)); return r;
}
__device__ __forceinline__ void upk2(u64t v, float& lo, float& hi) {
    asm("mov.b64 {%0,%1},%2;" : "=f"(lo), "=f"(hi) : "l"(v));
}
__device__ __forceinline__ u64t mul2_(u64t a, u64t b) {
    u64t r; asm("mul.rn.f32x2 %0,%1,%2;" : "=l"(r) : "l"(a), "l"(b)); return r;
}
__device__ __forceinline__ u64t fma2_(u64t a, u64t b, u64t c) {
    u64t r; asm("fma.rn.f32x2 %0,%1,%2,%3;" : "=l"(r) : "l"(a), "l"(b), "l"(c)); return r;
}

// runtime seq -> spatial map (flip folded in)
__device__ __forceinline__ int sp_map(int l, int dir) {
    if (dir & 1) l = L_TOT - 1 - l;
    int i0 = l % 24;
    int t  = l / 24;
    int i1 = t % 24;
    int i2 = t / 24;
    int m0, m1, m2;
    switch (dir >> 1) {
        case 0:  m0 = 1;   m1 = 576; m2 = 24;  break;
        case 1:  m0 = 1;   m1 = 24;  m2 = 576; break;
        case 2:  m0 = 576; m1 = 24;  m2 = 1;   break;
        default: m0 = 24;  m1 = 1;   m2 = 576; break;
    }
    return i0 * m0 + i1 * m1 + i2 * m2;
}

// all-576-block barrier; monotonic counter => safe across graph replays
__device__ __forceinline__ void grid_bar(int slot) {
    __syncthreads();
    if (threadIdx.x == 0) {
        __threadfence();
        unsigned old = atomicAdd((unsigned*)(g_barc + slot), 1u);
        unsigned target = old - (old % NCH) + NCH;
        while (g_barc[slot] < target) __nanosleep(32);
        __threadfence();
    }
    __syncthreads();
}

// ---------------- K0: in_proj (lane-regrouped 6x4 tiles) ------------------
__global__ void __launch_bounds__(256) k_inproj(const float* __restrict__ x,
                                                const float* __restrict__ Win) {
    __shared__ float xs[24 * 132];
    const int tid = threadIdx.x;
    const int s0 = blockIdx.x * 24;
    for (int j = tid; j < 24 * DM; j += 256) {
        int si = j >> 7, c = j & 127;
        xs[si * 132 + c] = x[(s0 + si) * DM + c];
    }
    __syncthreads();

    const int cg = tid >> 2;   // 0..63 -> output cols 4cg..4cg+3 (of 256)
    const int rg = tid & 3;    // rows rg + 4r, r = 0..5
    float acc[6][4];
#pragma unroll
    for (int r = 0; r < 6; r++)
#pragma unroll
        for (int c = 0; c < 4; c++) acc[r][c] = 0.f;

    const float4* W4 = (const float4*)Win;
    for (int k4 = 0; k4 < 32; k4++) {
        float4 yv[6];
#pragma unroll
        for (int r = 0; r < 6; r++)
            yv[r] = *(const float4*)(xs + (rg + 4 * r) * 132 + 4 * k4);
#pragma unroll
        for (int c = 0; c < 4; c++) {
            float4 w = W4[(4 * cg + c) * 32 + k4];
#pragma unroll
            for (int r = 0; r < 6; r++)
                acc[r][c] = fmaf(w.x, yv[r].x, fmaf(w.y, yv[r].y,
                            fmaf(w.z, yv[r].z, fmaf(w.w, yv[r].w, acc[r][c]))));
        }
    }

    int e0 = 4 * cg;
#pragma unroll
    for (int r = 0; r < 6; r++) {
        int row = s0 + rg + 4 * r;
        if (e0 < DM) {
            *(float4*)(g_xp + row * DM + e0) =
                make_float4(acc[r][0], acc[r][1], acc[r][2], acc[r][3]);
        } else {
            *(float4*)(g_z + row * DM + e0 - DM) =
                make_float4(siluf(acc[r][0]), siluf(acc[r][1]),
                            siluf(acc[r][2]), siluf(acc[r][3]));
        }
    }
}

// ---------------- K0b: depthwise conv + silu ----------------
__global__ void __launch_bounds__(512) k_conv(const float* __restrict__ cw,
                                              const float* __restrict__ cb) {
    __shared__ float cws[DM * 27];
    int tid = threadIdx.x;
    for (int j = tid; j < DM * 27; j += 512) cws[j] = cw[j];
    __syncthreads();
    int c = tid & 127;
    int s = blockIdx.x * 4 + (tid >> 7);
    int d0 = s % 24, t = s / 24, w0 = t % 24, h0 = t / 24;
    float acc = cb[c];
#pragma unroll
    for (int kh = 0; kh < 3; kh++) {
        int hh = h0 + kh - 1; if ((unsigned)hh >= 24u) continue;
#pragma unroll
        for (int kw = 0; kw < 3; kw++) {
            int ww = w0 + kw - 1; if ((unsigned)ww >= 24u) continue;
#pragma unroll
            for (int kd = 0; kd < 3; kd++) {
                int dd = d0 + kd - 1; if ((unsigned)dd >= 24u) continue;
                acc = fmaf(cws[c * 27 + kh * 9 + kw * 3 + kd],
                           g_xp[((hh * 24 + ww) * 24 + dd) * DM + c], acc);
            }
        }
    }
    g_buf[0][s * DM + c] = siluf(acc);
}

// ---------------- persistent all-directions kernel -----------------------
// smem layout (floats):
#define SM_BC   0                          // [24*32]  C/B rows, persists all phases
#define SM_U    768                        // [24][132] u tile, l-major (conflict-free)
#define SM_W    (SM_U + 24 * 132)          // [128][41] W transposed (k-major)
#define SM_XD   (SM_W + 128 * 41)          // [40][28]
#define SM_DTW  (SM_XD + 40 * 28)          // [128][9]
#define SM_BIAS (SM_DTW + 128 * 9)         // [128]
#define SM_Q    (SM_BIAS + 128)            // [24] ints
#define SMEM_FLOATS (SM_Q + 24)
// phase2 region (aliases phase1 scratch, starts at 768 => bc_s & q_s preserved)
#define SM_A2   768
#define SM_B2   (768 + NCH * 5)
#define SM_H2   (768 + 2 * NCH * 5)

__global__ void __launch_bounds__(128, 4) k_dirs(const float* __restrict__ xproj_w,
                                                 const float* __restrict__ dtw_g,
                                                 const float* __restrict__ dtb_g,
                                                 const float* __restrict__ Alog_g,
                                                 const float* __restrict__ Ds_g) {
    extern __shared__ float sm[];
    float* bc_s   = sm + SM_BC;
    float* u_s    = sm + SM_U;
    float* W_s    = sm + SM_W;
    float* xd_s   = sm + SM_XD;
    float* dtw_s  = sm + SM_DTW;
    float* bias_s = sm + SM_BIAS;
    int*   q_s    = (int*)(sm + SM_Q);

    const int tid = threadIdx.x;
    const int ci  = blockIdx.x;
    const int L0  = ci * CL;
    int bar = 0;

#pragma unroll 1
    for (int dir = 0; dir < 8; dir++) {
        const float* __restrict__ xin = g_buf[dir & 1];
        float* __restrict__ xout = g_buf[(dir + 1) & 1];

        // ---- phase 1: params + gather u + GEMM + dt/B/C + local scan ----
        if (tid < CL) q_s[tid] = sp_map(L0 + tid, dir);
        for (int j = tid; j < 40 * DM; j += 128) {
            int f = j >> 7, k = j & 127;
            W_s[k * 41 + f] = xproj_w[dir * 40 * DM + j];
        }
        for (int j = tid; j < DM * 8; j += 128)
            dtw_s[(j >> 3) * 9 + (j & 7)] = dtw_g[dir * DM * 8 + j];
        if (tid < DM) bias_s[tid] = dtb_g[dir * DM + tid];
        __syncthreads();

#pragma unroll
        for (int l = 0; l < CL; l++) u_s[l * 132 + tid] = xin[q_s[l] * DM + tid];
        __syncthreads();

        // xd(40x24) = W(40x128) @ u(128x24); 120 threads, 8 l's each
        if (tid < 120) {
            int f = tid % 40, lg = tid / 40, l0 = lg * 8;
            float acc[8];
#pragma unroll
            for (int i = 0; i < 8; i++) acc[i] = 0.f;
#pragma unroll 4
            for (int k4 = 0; k4 < 32; k4++) {
                float w0 = W_s[(4 * k4 + 0) * 41 + f];
                float w1 = W_s[(4 * k4 + 1) * 41 + f];
                float w2 = W_s[(4 * k4 + 2) * 41 + f];
                float w3 = W_s[(4 * k4 + 3) * 41 + f];
#pragma unroll
                for (int i = 0; i < 8; i++) {
                    float4 uv = *(const float4*)(u_s + (l0 + i) * 132 + 4 * k4);
                    acc[i] = fmaf(w0, uv.x, fmaf(w1, uv.y, fmaf(w2, uv.z, fmaf(w3, uv.w, acc[i]))));
                }
            }
#pragma unroll
            for (int i = 0; i < 8; i++) xd_s[f * 28 + l0 + i] = acc[i];
        }
        __syncthreads();
        for (int j = tid; j < CL * 32; j += 128)
            bc_s[j] = xd_s[(8 + (j & 31)) * 28 + (j >> 5)];
        __syncthreads();

        float A_[NST];
        {
            const float4* a4 = (const float4*)(Alog_g + (dir * DM + tid) * NST);
#pragma unroll
            for (int q = 0; q < 4; q++) {
                float4 v = a4[q];
                A_[4 * q]     = -__expf(v.x);
                A_[4 * q + 1] = -__expf(v.y);
                A_[4 * q + 2] = -__expf(v.z);
                A_[4 * q + 3] = -__expf(v.w);
            }
        }
        float A0 = A_[0];
        bool fast = true;
#pragma unroll
        for (int n = 0; n < NST; n++)
            if (fabsf(A_[n] - (float)(n + 1) * A0) > 1e-5f * fabsf(A_[n])) fast = false;
        float Dv = Ds_g[dir * DM + tid];

        float yv[CL], cumv[CL];
        float cum = 0.f;

        if (fast) {
            u64t h2[8];
#pragma unroll
            for (int k = 0; k < 8; k++) h2[k] = 0ull;
#pragma unroll
            for (int g = 0; g < 3; g++) {
                float dtl[8], e1l[8];
#pragma unroll
                for (int j = 0; j < 8; j++) {
                    int l = g * 8 + j;
                    float dtr = bias_s[tid];
#pragma unroll
                    for (int r = 0; r < 8; r++)
                        dtr = fmaf(dtw_s[tid * 9 + r], xd_s[r * 28 + l], dtr);
                    float dt = softplusf(dtr);
                    dtl[j] = dt;
                    e1l[j] = __expf(A0 * dt);
                }
#pragma unroll
                for (int j = 0; j < 8; j++) {
                    int l = g * 8 + j;
                    float u  = u_s[l * 132 + tid];
                    float dt = dtl[j];
                    float e1 = e1l[j];
                    cum += dt; cumv[l] = cum;
                    float e2 = e1 * e1, e4 = e2 * e2, e8 = e4 * e4;
                    u64t e4p = pk2(e4, e4), e8p = pk2(e8, e8);
                    u64t av[8];
                    av[0] = pk2(e1, e2);
                    av[1] = mul2_(av[0], pk2(e2, e2));
                    av[2] = mul2_(av[0], e4p);
                    av[3] = mul2_(av[1], e4p);
                    av[4] = mul2_(av[0], e8p);
                    av[5] = mul2_(av[1], e8p);
                    av[6] = mul2_(av[2], e8p);
                    av[7] = mul2_(av[3], e8p);
                    float dtu = dt * u;
                    u64t dtu2 = pk2(dtu, dtu);
                    const ulonglong2* Bq = (const ulonglong2*)(bc_s + l * 32);
                    u64t ya = 0ull, yb = 0ull;
#pragma unroll
                    for (int q = 0; q < 4; q++) {
                        ulonglong2 bb = Bq[q];
                        h2[2 * q]     = fma2_(av[2 * q],     h2[2 * q],     mul2_(dtu2, bb.x));
                        h2[2 * q + 1] = fma2_(av[2 * q + 1], h2[2 * q + 1], mul2_(dtu2, bb.y));
                    }
#pragma unroll
                    for (int q = 0; q < 4; q++) {
                        ulonglong2 cc = Bq[4 + q];
                        ya = fma2_(h2[2 * q],     cc.x, ya);
                        yb = fma2_(h2[2 * q + 1], cc.y, yb);
                    }
                    u64t ys = fma2_(ya, pk2(1.f, 1.f), yb);
                    float ylo, yhi; upk2(ys, ylo, yhi);
                    yv[l] = fmaf(u, Dv, ylo + yhi);
                }
            }
            float hv[NST];
#pragma unroll
            for (int k = 0; k < 8; k++) upk2(h2[k], hv[2 * k], hv[2 * k + 1]);
            float p1 = __expf(A0 * cum);
            float p2 = p1 * p1, p4 = p2 * p2, p8 = p4 * p4;
            float P[NST];
            P[0] = p1; P[1] = p2; P[2] = p2 * p1; P[3] = p4;
            P[4] = p4 * p1; P[5] = p4 * p2; P[6] = p4 * P[2]; P[7] = p8;
            P[8] = p8 * p1; P[9] = p8 * p2; P[10] = p8 * P[2]; P[11] = p8 * p4;
            P[12] = p8 * P[4]; P[13] = p8 * P[5]; P[14] = p8 * P[6]; P[15] = p8 * p8;
            float4* pa = (float4*)(g_Ach + ci * 2048 + tid * 16);
            float4* pb = (float4*)(g_Bch + ci * 2048 + tid * 16);
#pragma unroll
            for (int q = 0; q < 4; q++) {
                pa[q] = make_float4(P[4 * q], P[4 * q + 1], P[4 * q + 2], P[4 * q + 3]);
                pb[q] = make_float4(hv[4 * q], hv[4 * q + 1], hv[4 * q + 2], hv[4 * q + 3]);
            }
        } else {
            float h[NST];
#pragma unroll
            for (int n = 0; n < NST; n++) h[n] = 0.f;
#pragma unroll
            for (int l = 0; l < CL; l++) {
                float u = u_s[l * 132 + tid];
                float dtr = bias_s[tid];
#pragma unroll
                for (int r = 0; r < 8; r++) dtr = fmaf(dtw_s[tid * 9 + r], xd_s[r * 28 + l], dtr);
                float dt = softplusf(dtr);
                cum += dt; cumv[l] = cum;
                float dtu = dt * u;
                float y = u * Dv;
#pragma unroll
                for (int n = 0; n < NST; n++) {
                    h[n] = fmaf(__expf(A_[n] * dt), h[n], dtu * bc_s[l * 32 + n]);
                    y = fmaf(h[n], bc_s[l * 32 + 16 + n], y);
                }
                yv[l] = y;
            }
            float P[NST];
#pragma unroll
            for (int n = 0; n < NST; n++) P[n] = __expf(A_[n] * cum);
            float4* pa = (float4*)(g_Ach + ci * 2048 + tid * 16);
            float4* pb = (float4*)(g_Bch + ci * 2048 + tid * 16);
#pragma unroll
            for (int q = 0; q < 4; q++) {
                pa[q] = make_float4(P[4 * q], P[4 * q + 1], P[4 * q + 2], P[4 * q + 3]);
                pb[q] = make_float4(h[4 * q], h[4 * q + 1], h[4 * q + 2], h[4 * q + 3]);
            }
        }

        grid_bar(bar & 15); bar++;

        // ---- phase 2: exclusive prefix over 576 chunks (blocks 0..511) ----
        if (ci < 512) {
            float* A2 = sm + SM_A2;
            float* B2 = sm + SM_B2;
            float* H2 = sm + SM_H2;
            const int gw0 = ci * 4;
            for (int j = tid; j < NCH * 4; j += 128) {
                int c = j >> 2, w = j & 3;
                A2[c * 5 + w] = g_Ach[c * 2048 + gw0 + w];
                B2[c * 5 + w] = g_Bch[c * 2048 + gw0 + w];
            }
            __syncthreads();
            int w = tid >> 5, lane = tid & 31;
            const int PT = NCH / 32;     // 18
            float Ag = 1.f, Bg = 0.f;
            int c0 = lane * PT;
            for (int k = 0; k < PT; k++) {
                float a = A2[(c0 + k) * 5 + w];
                float b = B2[(c0 + k) * 5 + w];
                Bg = fmaf(a, Bg, b);
                Ag *= a;
            }
#pragma unroll
            for (int d = 1; d < 32; d <<= 1) {
                float aL = __shfl_up_sync(0xffffffffu, Ag, d);
                float bL = __shfl_up_sync(0xffffffffu, Bg, d);
                if (lane >= d) { Bg = fmaf(Ag, bL, Bg); Ag *= aL; }
            }
            float hp = __shfl_up_sync(0xffffffffu, Bg, 1);
            float h = (lane == 0) ? 0.f : hp;
            for (int k = 0; k < PT; k++) {
                H2[(c0 + k) * 5 + w] = h;
                h = fmaf(A2[(c0 + k) * 5 + w], h, B2[(c0 + k) * 5 + w]);
            }
            __syncthreads();
            for (int j = tid; j < NCH * 4; j += 128) {
                int c = j >> 2, w2 = j & 3;
                g_Hpref[c * 2048 + gw0 + w2] = H2[c * 5 + w2];
            }
        }

        grid_bar(bar & 15); bar++;

        // ---- phase 3: closed-form correction + scatter to spatial ----
        float h0[NST];
        {
            const float4* hp4 = (const float4*)(g_Hpref + ci * 2048 + tid * 16);
#pragma unroll
            for (int q = 0; q < 4; q++) {
                float4 v = hp4[q];
                h0[4 * q] = v.x; h0[4 * q + 1] = v.y; h0[4 * q + 2] = v.z; h0[4 * q + 3] = v.w;
            }
        }
        if (fast) {
            u64t h0p[8];
#pragma unroll
            for (int k = 0; k < 8; k++) h0p[k] = pk2(h0[2 * k], h0[2 * k + 1]);
#pragma unroll
            for (int l = 0; l < CL; l++) {
                float e1 = __expf(A0 * cumv[l]);
                float e2 = e1 * e1, e4 = e2 * e2, e8 = e4 * e4;
                u64t e4p = pk2(e4, e4), e8p = pk2(e8, e8);
                u64t av[8];
                av[0] = pk2(e1, e2);
                av[1] = mul2_(av[0], pk2(e2, e2));
                av[2] = mul2_(av[0], e4p);
                av[3] = mul2_(av[1], e4p);
                av[4] = mul2_(av[0], e8p);
                av[5] = mul2_(av[1], e8p);
                av[6] = mul2_(av[2], e8p);
                av[7] = mul2_(av[3], e8p);
                const ulonglong2* Cq = (const ulonglong2*)(bc_s + l * 32 + 16);
                u64t acc = 0ull;
#pragma unroll
                for (int q = 0; q < 4; q++) {
                    ulonglong2 cc = Cq[q];
                    acc = fma2_(mul2_(h0p[2 * q],     av[2 * q]),     cc.x, acc);
                    acc = fma2_(mul2_(h0p[2 * q + 1], av[2 * q + 1]), cc.y, acc);
                }
                float lo, hi; upk2(acc, lo, hi);
                xout[q_s[l] * DM + tid] = yv[l] + lo + hi;
            }
        } else {
#pragma unroll
            for (int l = 0; l < CL; l++) {
                float y = yv[l];
#pragma unroll
                for (int n = 0; n < NST; n++)
                    y = fmaf(h0[n] * __expf(A_[n] * cumv[l]), bc_s[l * 32 + 16 + n], y);
                xout[q_s[l] * DM + tid] = y;
            }
        }

        grid_bar(bar & 15); bar++;
    }
}

// ---------------- K4: LayerNorm + gate + out_proj (lane-regrouped 4x4) ----
__global__ void __launch_bounds__(256) k_final(const float* __restrict__ gamma,
                                               const float* __restrict__ beta,
                                               const float* __restrict__ Wout,
                                               float* __restrict__ out) {
    __shared__ float ym[32 * 132];
    const int tid = threadIdx.x;
    const int s0 = blockIdx.x * 32;

    for (int j = tid; j < 32 * DM; j += 256) {
        int si = j >> 7, c = j & 127;
        ym[si * 132 + c] = g_buf[0][(s0 + si) * DM + c];
    }
    __syncthreads();

    // LN stats: row = tid>>3 (0..31), 8 threads per row, 16 elems each
    {
        int row = tid >> 3;
        int sub = tid & 7;
        int c0 = sub * 16;
        float s = 0.f;
#pragma unroll
        for (int c = 0; c < 16; c++) s += ym[row * 132 + c0 + c];
#pragma unroll
        for (int d = 4; d; d >>= 1) s += __shfl_down_sync(0xffffffffu, s, d, 8);
        float m = __shfl_sync(0xffffffffu, s, 0, 8) * (1.f / DM);
        float v = 0.f;
#pragma unroll
        for (int c = 0; c < 16; c++) {
            float dcv = ym[row * 132 + c0 + c] - m;
            v = fmaf(dcv, dcv, v);
        }
#pragma unroll
        for (int d = 4; d; d >>= 1) v += __shfl_down_sync(0xffffffffu, v, d, 8);
        float r = rsqrtf(__shfl_sync(0xffffffffu, v, 0, 8) * (1.f / DM) + 1e-5f);
#pragma unroll
        for (int c = 0; c < 16; c++) {
            int cc = c0 + c;
            float val = (ym[row * 132 + cc] - m) * r * gamma[cc] + beta[cc];
            ym[row * 132 + cc] = val * g_z[(s0 + row) * DM + cc];
        }
    }
    __syncthreads();

    // GEMM: out[32 x 128] = ym @ Wout^T, 4x4 register tiles.
    // cg = tid>>3 (8 lanes share -> W loads 4 lines/warp); rg = tid&7,
    // rows {rg, rg+8, rg+16, rg+24} -> conflict-free LDS (stride 132).
    {
        int cg = tid >> 3;           // 0..31 -> cols 4cg..4cg+3
        int rg = tid & 7;
        float acc[4][4];
#pragma unroll
        for (int r = 0; r < 4; r++)
#pragma unroll
            for (int c = 0; c < 4; c++) acc[r][c] = 0.f;
        const float4* W4 = (const float4*)Wout;
        for (int k4 = 0; k4 < 32; k4++) {
            float4 y0 = *(const float4*)(ym + (rg     ) * 132 + 4 * k4);
            float4 y1 = *(const float4*)(ym + (rg +  8) * 132 + 4 * k4);
            float4 y2 = *(const float4*)(ym + (rg + 16) * 132 + 4 * k4);
            float4 y3 = *(const float4*)(ym + (rg + 24) * 132 + 4 * k4);
#pragma unroll
            for (int c = 0; c < 4; c++) {
                float4 w = W4[(4 * cg + c) * 32 + k4];
                acc[0][c] = fmaf(w.x, y0.x, fmaf(w.y, y0.y, fmaf(w.z, y0.z, fmaf(w.w, y0.w, acc[0][c]))));
                acc[1][c] = fmaf(w.x, y1.x, fmaf(w.y, y1.y, fmaf(w.z, y1.z, fmaf(w.w, y1.w, acc[1][c]))));
                acc[2][c] = fmaf(w.x, y2.x, fmaf(w.y, y2.y, fmaf(w.z, y2.z, fmaf(w.w, y2.w, acc[2][c]))));
                acc[3][c] = fmaf(w.x, y3.x, fmaf(w.y, y3.y, fmaf(w.z, y3.z, fmaf(w.w, y3.w, acc[3][c]))));
            }
        }
#pragma unroll
        for (int r = 0; r < 4; r++) {
            int row = s0 + rg + 8 * r;
            *(float4*)(out + row * DM + 4 * cg) =
                make_float4(acc[r][0], acc[r][1], acc[r][2], acc[r][3]);
        }
    }
}

// ---------------- launch ----------------
#define SMD (SMEM_FLOATS * 4)

extern "C" void kernel_launch(void* const* d_in, const int* in_sizes, int n_in,
                              void* d_out, int out_size) {
    const float* x         = (const float*)d_in[0];
    const float* in_proj_w = (const float*)d_in[1];
    const float* conv_w    = (const float*)d_in[2];
    const float* conv_b    = (const float*)d_in[3];
    const float* xproj_w   = (const float*)d_in[4];
    const float* dtw       = (const float*)d_in[5];
    const float* dtb       = (const float*)d_in[6];
    const float* A_logs    = (const float*)d_in[7];
    const float* Ds        = (const float*)d_in[8];
    const float* ln_g      = (const float*)d_in[9];
    const float* ln_b      = (const float*)d_in[10];
    const float* out_w     = (const float*)d_in[11];
    float* out = (float*)d_out;

    cudaFuncSetAttribute(k_dirs, cudaFuncAttributeMaxDynamicSharedMemorySize, SMD);

    k_inproj<<<L_TOT / 24, 256>>>(x, in_proj_w);
    k_conv<<<L_TOT / 4, 512>>>(conv_w, conv_b);

    k_dirs<<<NCH, 128, SMD>>>(xproj_w, dtw, dtb, A_logs, Ds);

    k_final<<<L_TOT / 32, 256>>>(ln_g, ln_b, out_w, out);
}

// round 17
// speedup vs baseline: 1.3352x; 1.0018x over previous
#include <cuda_runtime.h>
#include <math.h>

#define L_TOT 13824
#define CL    24
#define NCH   576
#define NCH4  (NCH * 4)
#define DM    128
#define NST   16

typedef unsigned long long u64t;

// ---------------- device scratch (static, no allocations) ----------------
__device__ float g_buf[2][L_TOT * DM];   // ping-pong xc buffers [S][128], spatial
__device__ float g_z[L_TOT * DM];        // silu(z)
__device__ float g_xp[L_TOT * DM];       // pre-conv x part
// aggregates in block-transposed tiles: [group=lane>>2][chunk][lane&3]
__device__ float g_Ach[512 * NCH4];
__device__ float g_Bch[512 * NCH4];
__device__ float g_Hpref[512 * NCH4];
__device__ volatile unsigned g_barc[16]; // monotonic grid-barrier counters

__device__ __forceinline__ float siluf(float v) { return v / (1.f + __expf(-v)); }
__device__ __forceinline__ float softplusf(float x) {
    if (x > 20.f) return x;
    return __logf(1.f + __expf(x));
}

// f32x2 packed helpers
__device__ __forceinline__ u64t pk2(float lo, float hi) {
    u64t r; asm("mov.b64 %0,{%1,%2};" : "=l"(r) : "f"(lo), "f"(hi)); return r;
}
__device__ __forceinline__ void upk2(u64t v, float& lo, float& hi) {
    asm("mov.b64 {%0,%1},%2;" : "=f"(lo), "=f"(hi) : "l"(v));
}
__device__ __forceinline__ u64t mul2_(u64t a, u64t b) {
    u64t r; asm("mul.rn.f32x2 %0,%1,%2;" : "=l"(r) : "l"(a), "l"(b)); return r;
}
__device__ __forceinline__ u64t fma2_(u64t a, u64t b, u64t c) {
    u64t r; asm("fma.rn.f32x2 %0,%1,%2,%3;" : "=l"(r) : "l"(a), "l"(b), "l"(c)); return r;
}

// runtime seq -> spatial map (flip folded in)
__device__ __forceinline__ int sp_map(int l, int dir) {
    if (dir & 1) l = L_TOT - 1 - l;
    int i0 = l % 24;
    int t  = l / 24;
    int i1 = t % 24;
    int i2 = t / 24;
    int m0, m1, m2;
    switch (dir >> 1) {
        case 0:  m0 = 1;   m1 = 576; m2 = 24;  break;
        case 1:  m0 = 1;   m1 = 24;  m2 = 576; break;
        case 2:  m0 = 576; m1 = 24;  m2 = 1;   break;
        default: m0 = 24;  m1 = 1;   m2 = 576; break;
    }
    return i0 * m0 + i1 * m1 + i2 * m2;
}

// all-576-block barrier; monotonic counter => safe across graph replays
__device__ __forceinline__ void grid_bar(int slot) {
    __syncthreads();
    if (threadIdx.x == 0) {
        __threadfence();
        unsigned old = atomicAdd((unsigned*)(g_barc + slot), 1u);
        unsigned target = old - (old % NCH) + NCH;
        while (g_barc[slot] < target) __nanosleep(32);
        __threadfence();
    }
    __syncthreads();
}

// ---------------- K0: in_proj (lane-regrouped 6x4 tiles) ------------------
__global__ void __launch_bounds__(256) k_inproj(const float* __restrict__ x,
                                                const float* __restrict__ Win) {
    __shared__ float xs[24 * 132];
    const int tid = threadIdx.x;
    const int s0 = blockIdx.x * 24;
    for (int j = tid; j < 24 * DM; j += 256) {
        int si = j >> 7, c = j & 127;
        xs[si * 132 + c] = x[(s0 + si) * DM + c];
    }
    __syncthreads();

    const int cg = tid >> 2;
    const int rg = tid & 3;
    float acc[6][4];
#pragma unroll
    for (int r = 0; r < 6; r++)
#pragma unroll
        for (int c = 0; c < 4; c++) acc[r][c] = 0.f;

    const float4* W4 = (const float4*)Win;
    for (int k4 = 0; k4 < 32; k4++) {
        float4 yv[6];
#pragma unroll
        for (int r = 0; r < 6; r++)
            yv[r] = *(const float4*)(xs + (rg + 4 * r) * 132 + 4 * k4);
#pragma unroll
        for (int c = 0; c < 4; c++) {
            float4 w = W4[(4 * cg + c) * 32 + k4];
#pragma unroll
            for (int r = 0; r < 6; r++)
                acc[r][c] = fmaf(w.x, yv[r].x, fmaf(w.y, yv[r].y,
                            fmaf(w.z, yv[r].z, fmaf(w.w, yv[r].w, acc[r][c]))));
        }
    }

    int e0 = 4 * cg;
#pragma unroll
    for (int r = 0; r < 6; r++) {
        int row = s0 + rg + 4 * r;
        if (e0 < DM) {
            *(float4*)(g_xp + row * DM + e0) =
                make_float4(acc[r][0], acc[r][1], acc[r][2], acc[r][3]);
        } else {
            *(float4*)(g_z + row * DM + e0 - DM) =
                make_float4(siluf(acc[r][0]), siluf(acc[r][1]),
                            siluf(acc[r][2]), siluf(acc[r][3]));
        }
    }
}

// ---------------- K0b: depthwise conv + silu ----------------
__global__ void __launch_bounds__(512) k_conv(const float* __restrict__ cw,
                                              const float* __restrict__ cb) {
    __shared__ float cws[DM * 27];
    int tid = threadIdx.x;
    for (int j = tid; j < DM * 27; j += 512) cws[j] = cw[j];
    __syncthreads();
    int c = tid & 127;
    int s = blockIdx.x * 4 + (tid >> 7);
    int d0 = s % 24, t = s / 24, w0 = t % 24, h0 = t / 24;
    float acc = cb[c];
#pragma unroll
    for (int kh = 0; kh < 3; kh++) {
        int hh = h0 + kh - 1; if ((unsigned)hh >= 24u) continue;
#pragma unroll
        for (int kw = 0; kw < 3; kw++) {
            int ww = w0 + kw - 1; if ((unsigned)ww >= 24u) continue;
#pragma unroll
            for (int kd = 0; kd < 3; kd++) {
                int dd = d0 + kd - 1; if ((unsigned)dd >= 24u) continue;
                acc = fmaf(cws[c * 27 + kh * 9 + kw * 3 + kd],
                           g_xp[((hh * 24 + ww) * 24 + dd) * DM + c], acc);
            }
        }
    }
    g_buf[0][s * DM + c] = siluf(acc);
}

// ---------------- persistent all-directions kernel -----------------------
#define SM_BC   0                          // [24*32]
#define SM_U    768                        // [24][132]
#define SM_W    (SM_U + 24 * 132)          // [128][41]
#define SM_XD   (SM_W + 128 * 41)          // [40][28]
#define SM_DTW  (SM_XD + 40 * 28)          // [128][9]
#define SM_BIAS (SM_DTW + 128 * 9)         // [128]
#define SM_Q    (SM_BIAS + 128)            // [24] ints
#define SMEM_FLOATS (SM_Q + 24)
// phase2 region aliases phase1 scratch (>=768): 3 x [576][5] = 8640 floats
#define SM_A2   768
#define SM_B2   (768 + NCH * 5)
#define SM_H2   (768 + 2 * NCH * 5)

__global__ void __launch_bounds__(128, 4) k_dirs(const float* __restrict__ xproj_w,
                                                 const float* __restrict__ dtw_g,
                                                 const float* __restrict__ dtb_g,
                                                 const float* __restrict__ Alog_g,
                                                 const float* __restrict__ Ds_g) {
    extern __shared__ float sm[];
    float* bc_s   = sm + SM_BC;
    float* u_s    = sm + SM_U;
    float* W_s    = sm + SM_W;
    float* xd_s   = sm + SM_XD;
    float* dtw_s  = sm + SM_DTW;
    float* bias_s = sm + SM_BIAS;
    int*   q_s    = (int*)(sm + SM_Q);

    const int tid = threadIdx.x;
    const int ci  = blockIdx.x;
    const int L0  = ci * CL;
    int bar = 0;

#pragma unroll 1
    for (int dir = 0; dir < 8; dir++) {
        const float* __restrict__ xin = g_buf[dir & 1];
        float* __restrict__ xout = g_buf[(dir + 1) & 1];

        // ---- phase 1: params + gather u + GEMM + dt/B/C + local scan ----
        if (tid < CL) q_s[tid] = sp_map(L0 + tid, dir);
        for (int j = tid; j < 40 * DM; j += 128) {
            int f = j >> 7, k = j & 127;
            W_s[k * 41 + f] = xproj_w[dir * 40 * DM + j];
        }
        for (int j = tid; j < DM * 8; j += 128)
            dtw_s[(j >> 3) * 9 + (j & 7)] = dtw_g[dir * DM * 8 + j];
        if (tid < DM) bias_s[tid] = dtb_g[dir * DM + tid];
        __syncthreads();

#pragma unroll
        for (int l = 0; l < CL; l++) u_s[l * 132 + tid] = xin[q_s[l] * DM + tid];
        __syncthreads();

        // xd(40x24) = W(40x128) @ u(128x24); 120 threads, 8 l's each
        if (tid < 120) {
            int f = tid % 40, lg = tid / 40, l0 = lg * 8;
            float acc[8];
#pragma unroll
            for (int i = 0; i < 8; i++) acc[i] = 0.f;
#pragma unroll 4
            for (int k4 = 0; k4 < 32; k4++) {
                float w0 = W_s[(4 * k4 + 0) * 41 + f];
                float w1 = W_s[(4 * k4 + 1) * 41 + f];
                float w2 = W_s[(4 * k4 + 2) * 41 + f];
                float w3 = W_s[(4 * k4 + 3) * 41 + f];
#pragma unroll
                for (int i = 0; i < 8; i++) {
                    float4 uv = *(const float4*)(u_s + (l0 + i) * 132 + 4 * k4);
                    acc[i] = fmaf(w0, uv.x, fmaf(w1, uv.y, fmaf(w2, uv.z, fmaf(w3, uv.w, acc[i]))));
                }
            }
#pragma unroll
            for (int i = 0; i < 8; i++) xd_s[f * 28 + l0 + i] = acc[i];
        }
        __syncthreads();
        for (int j = tid; j < CL * 32; j += 128)
            bc_s[j] = xd_s[(8 + (j & 31)) * 28 + (j >> 5)];
        __syncthreads();

        float A_[NST];
        {
            const float4* a4 = (const float4*)(Alog_g + (dir * DM + tid) * NST);
#pragma unroll
            for (int q = 0; q < 4; q++) {
                float4 v = a4[q];
                A_[4 * q]     = -__expf(v.x);
                A_[4 * q + 1] = -__expf(v.y);
                A_[4 * q + 2] = -__expf(v.z);
                A_[4 * q + 3] = -__expf(v.w);
            }
        }
        float A0 = A_[0];
        bool fast = true;
#pragma unroll
        for (int n = 0; n < NST; n++)
            if (fabsf(A_[n] - (float)(n + 1) * A0) > 1e-5f * fabsf(A_[n])) fast = false;
        float Dv = Ds_g[dir * DM + tid];

        float yv[CL], cumv[CL];
        float cum = 0.f;

        if (fast) {
            u64t h2[8];
#pragma unroll
            for (int k = 0; k < 8; k++) h2[k] = 0ull;
#pragma unroll
            for (int g = 0; g < 3; g++) {
                float dtl[8], e1l[8];
#pragma unroll
                for (int j = 0; j < 8; j++) {
                    int l = g * 8 + j;
                    float dtr = bias_s[tid];
#pragma unroll
                    for (int r = 0; r < 8; r++)
                        dtr = fmaf(dtw_s[tid * 9 + r], xd_s[r * 28 + l], dtr);
                    float dt = softplusf(dtr);
                    dtl[j] = dt;
                    e1l[j] = __expf(A0 * dt);
                }
#pragma unroll
                for (int j = 0; j < 8; j++) {
                    int l = g * 8 + j;
                    float u  = u_s[l * 132 + tid];
                    float dt = dtl[j];
                    float e1 = e1l[j];
                    cum += dt; cumv[l] = cum;
                    float e2 = e1 * e1, e4 = e2 * e2, e8 = e4 * e4;
                    u64t e4p = pk2(e4, e4), e8p = pk2(e8, e8);
                    u64t av[8];
                    av[0] = pk2(e1, e2);
                    av[1] = mul2_(av[0], pk2(e2, e2));
                    av[2] = mul2_(av[0], e4p);
                    av[3] = mul2_(av[1], e4p);
                    av[4] = mul2_(av[0], e8p);
                    av[5] = mul2_(av[1], e8p);
                    av[6] = mul2_(av[2], e8p);
                    av[7] = mul2_(av[3], e8p);
                    float dtu = dt * u;
                    u64t dtu2 = pk2(dtu, dtu);
                    const ulonglong2* Bq = (const ulonglong2*)(bc_s + l * 32);
                    u64t ya = 0ull, yb = 0ull;
#pragma unroll
                    for (int q = 0; q < 4; q++) {
                        ulonglong2 bb = Bq[q];
                        h2[2 * q]     = fma2_(av[2 * q],     h2[2 * q],     mul2_(dtu2, bb.x));
                        h2[2 * q + 1] = fma2_(av[2 * q + 1], h2[2 * q + 1], mul2_(dtu2, bb.y));
                    }
#pragma unroll
                    for (int q = 0; q < 4; q++) {
                        ulonglong2 cc = Bq[4 + q];
                        ya = fma2_(h2[2 * q],     cc.x, ya);
                        yb = fma2_(h2[2 * q + 1], cc.y, yb);
                    }
                    u64t ys = fma2_(ya, pk2(1.f, 1.f), yb);
                    float ylo, yhi; upk2(ys, ylo, yhi);
                    yv[l] = fmaf(u, Dv, ylo + yhi);
                }
            }
            float hv[NST];
#pragma unroll
            for (int k = 0; k < 8; k++) upk2(h2[k], hv[2 * k], hv[2 * k + 1]);
            float p1 = __expf(A0 * cum);
            float p2 = p1 * p1, p4 = p2 * p2, p8 = p4 * p4;
            float P[NST];
            P[0] = p1; P[1] = p2; P[2] = p2 * p1; P[3] = p4;
            P[4] = p4 * p1; P[5] = p4 * p2; P[6] = p4 * P[2]; P[7] = p8;
            P[8] = p8 * p1; P[9] = p8 * p2; P[10] = p8 * P[2]; P[11] = p8 * p4;
            P[12] = p8 * P[4]; P[13] = p8 * P[5]; P[14] = p8 * P[6]; P[15] = p8 * p8;
#pragma unroll
            for (int q = 0; q < 4; q++) {
                int g2 = tid * 4 + q;
                *(float4*)(g_Ach + g2 * NCH4 + ci * 4) =
                    make_float4(P[4 * q], P[4 * q + 1], P[4 * q + 2], P[4 * q + 3]);
                *(float4*)(g_Bch + g2 * NCH4 + ci * 4) =
                    make_float4(hv[4 * q], hv[4 * q + 1], hv[4 * q + 2], hv[4 * q + 3]);
            }
        } else {
            float h[NST];
#pragma unroll
            for (int n = 0; n < NST; n++) h[n] = 0.f;
#pragma unroll
            for (int l = 0; l < CL; l++) {
                float u = u_s[l * 132 + tid];
                float dtr = bias_s[tid];
#pragma unroll
                for (int r = 0; r < 8; r++) dtr = fmaf(dtw_s[tid * 9 + r], xd_s[r * 28 + l], dtr);
                float dt = softplusf(dtr);
                cum += dt; cumv[l] = cum;
                float dtu = dt * u;
                float y = u * Dv;
#pragma unroll
                for (int n = 0; n < NST; n++) {
                    h[n] = fmaf(__expf(A_[n] * dt), h[n], dtu * bc_s[l * 32 + n]);
                    y = fmaf(h[n], bc_s[l * 32 + 16 + n], y);
                }
                yv[l] = y;
            }
            float P[NST];
#pragma unroll
            for (int n = 0; n < NST; n++) P[n] = __expf(A_[n] * cum);
#pragma unroll
            for (int q = 0; q < 4; q++) {
                int g2 = tid * 4 + q;
                *(float4*)(g_Ach + g2 * NCH4 + ci * 4) =
                    make_float4(P[4 * q], P[4 * q + 1], P[4 * q + 2], P[4 * q + 3]);
                *(float4*)(g_Bch + g2 * NCH4 + ci * 4) =
                    make_float4(h[4 * q], h[4 * q + 1], h[4 * q + 2], h[4 * q + 3]);
            }
        }

        grid_bar(bar & 15); bar++;

        // ---- phase 2: exclusive prefix; block ci handles lane-group ci ----
        if (ci < 512) {
            float* A2 = sm + SM_A2;
            float* B2 = sm + SM_B2;
            float* H2 = sm + SM_H2;
            const float* __restrict__ srcA = g_Ach + ci * NCH4;
            const float* __restrict__ srcB = g_Bch + ci * NCH4;
            for (int j = tid; j < NCH4; j += 128) {
                int c = j >> 2, w = j & 3;
                A2[c * 5 + w] = srcA[j];
                B2[c * 5 + w] = srcB[j];
            }
            __syncthreads();
            int w = tid >> 5, lane = tid & 31;
            const int PT = NCH / 32;     // 18
            float Ag = 1.f, Bg = 0.f;
            int c0 = lane * PT;
            for (int k = 0; k < PT; k++) {
                float a = A2[(c0 + k) * 5 + w];
                float b = B2[(c0 + k) * 5 + w];
                Bg = fmaf(a, Bg, b);
                Ag *= a;
            }
#pragma unroll
            for (int d = 1; d < 32; d <<= 1) {
                float aL = __shfl_up_sync(0xffffffffu, Ag, d);
                float bL = __shfl_up_sync(0xffffffffu, Bg, d);
                if (lane >= d) { Bg = fmaf(Ag, bL, Bg); Ag *= aL; }
            }
            float hp = __shfl_up_sync(0xffffffffu, Bg, 1);
            float h = (lane == 0) ? 0.f : hp;
            for (int k = 0; k < PT; k++) {
                H2[(c0 + k) * 5 + w] = h;
                h = fmaf(A2[(c0 + k) * 5 + w], h, B2[(c0 + k) * 5 + w]);
            }
            __syncthreads();
            float* __restrict__ dstH = g_Hpref + ci * NCH4;
            for (int j = tid; j < NCH4; j += 128) {
                int c = j >> 2, w2 = j & 3;
                dstH[j] = H2[c * 5 + w2];
            }
        }

        grid_bar(bar & 15); bar++;

        // ---- phase 3: closed-form correction + scatter to spatial ----
        float h0[NST];
#pragma unroll
        for (int q = 0; q < 4; q++) {
            float4 v = *(const float4*)(g_Hpref + (tid * 4 + q) * NCH4 + ci * 4);
            h0[4 * q] = v.x; h0[4 * q + 1] = v.y; h0[4 * q + 2] = v.z; h0[4 * q + 3] = v.w;
        }
        if (fast) {
            u64t h0p[8];
#pragma unroll
            for (int k = 0; k < 8; k++) h0p[k] = pk2(h0[2 * k], h0[2 * k + 1]);
#pragma unroll
            for (int l = 0; l < CL; l++) {
                float e1 = __expf(A0 * cumv[l]);
                float e2 = e1 * e1, e4 = e2 * e2, e8 = e4 * e4;
                u64t e4p = pk2(e4, e4), e8p = pk2(e8, e8);
                u64t av[8];
                av[0] = pk2(e1, e2);
                av[1] = mul2_(av[0], pk2(e2, e2));
                av[2] = mul2_(av[0], e4p);
                av[3] = mul2_(av[1], e4p);
                av[4] = mul2_(av[0], e8p);
                av[5] = mul2_(av[1], e8p);
                av[6] = mul2_(av[2], e8p);
                av[7] = mul2_(av[3], e8p);
                const ulonglong2* Cq = (const ulonglong2*)(bc_s + l * 32 + 16);
                u64t acc = 0ull;
#pragma unroll
                for (int q = 0; q < 4; q++) {
                    ulonglong2 cc = Cq[q];
                    acc = fma2_(mul2_(h0p[2 * q],     av[2 * q]),     cc.x, acc);
                    acc = fma2_(mul2_(h0p[2 * q + 1], av[2 * q + 1]), cc.y, acc);
                }
                float lo, hi; upk2(acc, lo, hi);
                xout[q_s[l] * DM + tid] = yv[l] + lo + hi;
            }
        } else {
#pragma unroll
            for (int l = 0; l < CL; l++) {
                float y = yv[l];
#pragma unroll
                for (int n = 0; n < NST; n++)
                    y = fmaf(h0[n] * __expf(A_[n] * cumv[l]), bc_s[l * 32 + 16 + n], y);
                xout[q_s[l] * DM + tid] = y;
            }
        }

        grid_bar(bar & 15); bar++;
    }
}

// ---------------- K4: LayerNorm + gate + out_proj (lane-regrouped 4x4) ----
__global__ void __launch_bounds__(256) k_final(const float* __restrict__ gamma,
                                               const float* __restrict__ beta,
                                               const float* __restrict__ Wout,
                                               float* __restrict__ out) {
    __shared__ float ym[32 * 132];
    const int tid = threadIdx.x;
    const int s0 = blockIdx.x * 32;

    for (int j = tid; j < 32 * DM; j += 256) {
        int si = j >> 7, c = j & 127;
        ym[si * 132 + c] = g_buf[0][(s0 + si) * DM + c];
    }
    __syncthreads();

    // LN stats: row = tid>>3 (0..31), 8 threads per row, 16 elems (4 float4) each
    {
        int row = tid >> 3;
        int sub = tid & 7;
        int c0 = sub * 16;
        float4 v4[4];
#pragma unroll
        for (int q = 0; q < 4; q++) v4[q] = *(const float4*)(ym + row * 132 + c0 + 4 * q);
        float s = 0.f;
#pragma unroll
        for (int q = 0; q < 4; q++) s += v4[q].x + v4[q].y + v4[q].z + v4[q].w;
#pragma unroll
        for (int d = 4; d; d >>= 1) s += __shfl_down_sync(0xffffffffu, s, d, 8);
        float m = __shfl_sync(0xffffffffu, s, 0, 8) * (1.f / DM);
        float v = 0.f;
#pragma unroll
        for (int q = 0; q < 4; q++) {
            float a0 = v4[q].x - m, a1 = v4[q].y - m, a2 = v4[q].z - m, a3 = v4[q].w - m;
            v = fmaf(a0, a0, fmaf(a1, a1, fmaf(a2, a2, fmaf(a3, a3, v))));
        }
#pragma unroll
        for (int d = 4; d; d >>= 1) v += __shfl_down_sync(0xffffffffu, v, d, 8);
        float r = rsqrtf(__shfl_sync(0xffffffffu, v, 0, 8) * (1.f / DM) + 1e-5f);
#pragma unroll
        for (int q = 0; q < 4; q++) {
            int cc = c0 + 4 * q;
            float4 gm = *(const float4*)(gamma + cc);
            float4 bt = *(const float4*)(beta + cc);
            float4 zz = *(const float4*)(g_z + (s0 + row) * DM + cc);
            float4 o;
            o.x = fmaf((v4[q].x - m) * r, gm.x, bt.x) * zz.x;
            o.y = fmaf((v4[q].y - m) * r, gm.y, bt.y) * zz.y;
            o.z = fmaf((v4[q].z - m) * r, gm.z, bt.z) * zz.z;
            o.w = fmaf((v4[q].w - m) * r, gm.w, bt.w) * zz.w;
            *(float4*)(ym + row * 132 + cc) = o;
        }
    }
    __syncthreads();

    // GEMM: out[32 x 128] = ym @ Wout^T, 4x4 register tiles
    {
        int cg = tid >> 3;
        int rg = tid & 7;
        float acc[4][4];
#pragma unroll
        for (int r = 0; r < 4; r++)
#pragma unroll
            for (int c = 0; c < 4; c++) acc[r][c] = 0.f;
        const float4* W4 = (const float4*)Wout;
        for (int k4 = 0; k4 < 32; k4++) {
            float4 y0 = *(const float4*)(ym + (rg     ) * 132 + 4 * k4);
            float4 y1 = *(const float4*)(ym + (rg +  8) * 132 + 4 * k4);
            float4 y2 = *(const float4*)(ym + (rg + 16) * 132 + 4 * k4);
            float4 y3 = *(const float4*)(ym + (rg + 24) * 132 + 4 * k4);
#pragma unroll
            for (int c = 0; c < 4; c++) {
                float4 w = W4[(4 * cg + c) * 32 + k4];
                acc[0][c] = fmaf(w.x, y0.x, fmaf(w.y, y0.y, fmaf(w.z, y0.z, fmaf(w.w, y0.w, acc[0][c]))));
                acc[1][c] = fmaf(w.x, y1.x, fmaf(w.y, y1.y, fmaf(w.z, y1.z, fmaf(w.w, y1.w, acc[1][c]))));
                acc[2][c] = fmaf(w.x, y2.x, fmaf(w.y, y2.y, fmaf(w.z, y2.z, fmaf(w.w, y2.w, acc[2][c]))));
                acc[3][c] = fmaf(w.x, y3.x, fmaf(w.y, y3.y, fmaf(w.z, y3.z, fmaf(w.w, y3.w, acc[3][c]))));
            }
        }
#pragma unroll
        for (int r = 0; r < 4; r++) {
            int row = s0 + rg + 8 * r;
            *(float4*)(out + row * DM + 4 * cg) =
                make_float4(acc[r][0], acc[r][1], acc[r][2], acc[r][3]);
        }
    }
}

// ---------------- launch ----------------
#define SMD (SMEM_FLOATS * 4)

extern "C" void kernel_launch(void* const* d_in, const int* in_sizes, int n_in,
                              void* d_out, int out_size) {
    const float* x         = (const float*)d_in[0];
    const float* in_proj_w = (const float*)d_in[1];
    const float* conv_w    = (const float*)d_in[2];
    const float* conv_b    = (const float*)d_in[3];
    const float* xproj_w   = (const float*)d_in[4];
    const float* dtw       = (const float*)d_in[5];
    const float* dtb       = (const float*)d_in[6];
    const float* A_logs    = (const float*)d_in[7];
    const float* Ds        = (const float*)d_in[8];
    const float* ln_g      = (const float*)d_in[9];
    const float* ln_b      = (const float*)d_in[10];
    const float* out_w     = (const float*)d_in[11];
    float* out = (float*)d_out;

    cudaFuncSetAttribute(k_dirs, cudaFuncAttributeMaxDynamicSharedMemorySize, SMD);

    k_inproj<<<L_TOT / 24, 256>>>(x, in_proj_w);
    k_conv<<<L_TOT / 4, 512>>>(conv_w, conv_b);

    k_dirs<<<NCH, 128, SMD>>>(xproj_w, dtw, dtb, A_logs, Ds);

    k_final<<<L_TOT / 32, 256>>>(ln_g, ln_b, out_w, out);
}